// round 1
// baseline (speedup 1.0000x reference)
#include <cuda_runtime.h>
#include <math.h>

#define B_  4
#define S_  2048
#define D_  1024
#define M_  512
#define H_  8
#define DK_ 64
#define R_  (B_*S_)   // 8192 token rows

// ---------------- scratch (device globals: no allocation) ----------------
__device__ float g_mem[R_*M_];
__device__ float g_q  [R_*M_];
__device__ float g_k  [R_*M_];
__device__ float g_v  [R_*M_];
__device__ float g_ctx[R_*M_];
__device__ float g_att[R_*M_];
__device__ float g_h1 [R_*D_];
__device__ float g_h2 [R_*D_];

__device__ __forceinline__ float gelu_exact(float v) {
    return 0.5f * v * (1.0f + erff(v * 0.70710678118654752440f));
}

// ---------------- SGEMM: C[M,N] = A[M,K] @ B[K,N] (+bias / epilogues) ------
// 128x128 block tile, BK=16, 256 threads, 8x8 per-thread microtile.
// EPI 0: C = acc + bias[c]
// EPI 1: QKV scatter: out[((b*8+h)*2048+s)*64+d] = acc + bias[c]
// EPI 2: C = gelu(C + acc)   (accumulate into prior pass, then GELU)
template<int EPI>
__global__ __launch_bounds__(256, 2)
void sgemm128(const float* __restrict__ A, const float* __restrict__ Bm,
              const float* __restrict__ bias, float* __restrict__ C,
              int M, int N, int K)
{
    __shared__ __align__(16) float As[16*128];
    __shared__ __align__(16) float Bs[16*128];

    const int tid  = threadIdx.x;
    const int bm   = blockIdx.y * 128;
    const int bn   = blockIdx.x * 128;
    const int arow = tid >> 2;          // 0..63
    const int acol = (tid & 3) << 2;    // 0,4,8,12
    const int brow = tid >> 5;          // 0..7
    const int bcol = (tid & 31) << 2;   // 0..124
    const int tx   = tid & 15;
    const int ty   = tid >> 4;

    const float* Ap = A  + (size_t)(bm + arow) * K + acol;
    const float* Bp = Bm + (size_t)brow * N + bn + bcol;

    float acc[8][8];
#pragma unroll
    for (int i = 0; i < 8; i++)
#pragma unroll
        for (int j = 0; j < 8; j++) acc[i][j] = 0.f;

    for (int k0 = 0; k0 < K; k0 += 16) {
        float4 a0 = *reinterpret_cast<const float4*>(Ap);
        float4 a1 = *reinterpret_cast<const float4*>(Ap + (size_t)64 * K);
        float4 b0 = *reinterpret_cast<const float4*>(Bp);
        float4 b1 = *reinterpret_cast<const float4*>(Bp + (size_t)8 * N);
        __syncthreads();  // previous tile fully consumed
        As[(acol+0)*128 + arow     ] = a0.x;
        As[(acol+1)*128 + arow     ] = a0.y;
        As[(acol+2)*128 + arow     ] = a0.z;
        As[(acol+3)*128 + arow     ] = a0.w;
        As[(acol+0)*128 + arow + 64] = a1.x;
        As[(acol+1)*128 + arow + 64] = a1.y;
        As[(acol+2)*128 + arow + 64] = a1.z;
        As[(acol+3)*128 + arow + 64] = a1.w;
        *reinterpret_cast<float4*>(&Bs[ brow     *128 + bcol]) = b0;
        *reinterpret_cast<float4*>(&Bs[(brow + 8)*128 + bcol]) = b1;
        __syncthreads();
#pragma unroll
        for (int k = 0; k < 16; k++) {
            float4 aA = *reinterpret_cast<const float4*>(&As[k*128 + ty*8    ]);
            float4 aB = *reinterpret_cast<const float4*>(&As[k*128 + ty*8 + 4]);
            float4 bA = *reinterpret_cast<const float4*>(&Bs[k*128 + tx*8    ]);
            float4 bB = *reinterpret_cast<const float4*>(&Bs[k*128 + tx*8 + 4]);
            float av[8] = {aA.x, aA.y, aA.z, aA.w, aB.x, aB.y, aB.z, aB.w};
            float bv[8] = {bA.x, bA.y, bA.z, bA.w, bB.x, bB.y, bB.z, bB.w};
#pragma unroll
            for (int i = 0; i < 8; i++)
#pragma unroll
                for (int j = 0; j < 8; j++) acc[i][j] += av[i] * bv[j];
        }
        Ap += 16;
        Bp += (size_t)16 * N;
    }

    const int c0 = bn + tx * 8;
    float bv8[8];
    if (EPI != 2) {
#pragma unroll
        for (int j = 0; j < 8; j++) bv8[j] = bias[c0 + j];
    }
#pragma unroll
    for (int i = 0; i < 8; i++) {
        const int r = bm + ty * 8 + i;
        if (EPI == 0) {
            float* cp = C + (size_t)r * N + c0;
            float4 o0 = make_float4(acc[i][0]+bv8[0], acc[i][1]+bv8[1],
                                    acc[i][2]+bv8[2], acc[i][3]+bv8[3]);
            float4 o1 = make_float4(acc[i][4]+bv8[4], acc[i][5]+bv8[5],
                                    acc[i][6]+bv8[6], acc[i][7]+bv8[7]);
            *reinterpret_cast<float4*>(cp)     = o0;
            *reinterpret_cast<float4*>(cp + 4) = o1;
        } else if (EPI == 1) {
            const int bb = r >> 11, ss = r & 2047;
            const int hh = c0 >> 6, dd = c0 & 63;
            float* cp = C + ((size_t)((bb*8 + hh)*2048 + ss))*64 + dd;
            float4 o0 = make_float4(acc[i][0]+bv8[0], acc[i][1]+bv8[1],
                                    acc[i][2]+bv8[2], acc[i][3]+bv8[3]);
            float4 o1 = make_float4(acc[i][4]+bv8[4], acc[i][5]+bv8[5],
                                    acc[i][6]+bv8[6], acc[i][7]+bv8[7]);
            *reinterpret_cast<float4*>(cp)     = o0;
            *reinterpret_cast<float4*>(cp + 4) = o1;
        } else {  // EPI == 2: accumulate + GELU
            float* cp = C + (size_t)r * N + c0;
            float4 e0 = *reinterpret_cast<const float4*>(cp);
            float4 e1 = *reinterpret_cast<const float4*>(cp + 4);
            e0.x = gelu_exact(e0.x + acc[i][0]);
            e0.y = gelu_exact(e0.y + acc[i][1]);
            e0.z = gelu_exact(e0.z + acc[i][2]);
            e0.w = gelu_exact(e0.w + acc[i][3]);
            e1.x = gelu_exact(e1.x + acc[i][4]);
            e1.y = gelu_exact(e1.y + acc[i][5]);
            e1.z = gelu_exact(e1.z + acc[i][6]);
            e1.w = gelu_exact(e1.w + acc[i][7]);
            *reinterpret_cast<float4*>(cp)     = e0;
            *reinterpret_cast<float4*>(cp + 4) = e1;
        }
    }
}

// ---------------- flash attention (fp32, online softmax) -----------------
// grid (S/64, B*H); 256 threads = 8 warps; each warp owns 8 queries.
// Per key-chunk of 64: per-lane 8q x 2k register tile (10 LDS / 16 FMA).
#define ATTN_SMEM ((64*64 + 64*65 + 64*64 + 64*64) * 4)

__global__ __launch_bounds__(256)
void attn_kernel(const float* __restrict__ Qg, const float* __restrict__ Kg,
                 const float* __restrict__ Vg, const float* __restrict__ ocr,
                 float* __restrict__ ctx)
{
    extern __shared__ float sm[];
    float* q_sh = sm;                       // 64q x 64d
    float* ks   = sm + 4096;                // 64d x 64k, pitch 65
    float* vs   = sm + 4096 + 4160;         // 64k x 64d
    float* p_sh = sm + 4096 + 4160 + 4096;  // 64q x 64k

    const int tid  = threadIdx.x;
    const int w    = tid >> 5, lane = tid & 31;
    const int bh   = blockIdx.y;
    const int b    = bh >> 3, h = bh & 7;
    const int qb   = blockIdx.x * 64;
    const float hb = ocr[h];   // per-head scalar bias (softmax-invariant, added for fidelity)

    const float* Qp = Qg + (size_t)bh * S_ * 64;
    const float* Kp = Kg + (size_t)bh * S_ * 64;
    const float* Vp = Vg + (size_t)bh * S_ * 64;

    {   // load query tile (contiguous)
        const float4* src = reinterpret_cast<const float4*>(Qp + (size_t)qb * 64);
        float4* dst = reinterpret_cast<float4*>(q_sh);
        for (int i = tid; i < 1024; i += 256) dst[i] = src[i];
    }

    float m_i[8], l_i[8], o0[8], o1[8];
#pragma unroll
    for (int qq = 0; qq < 8; qq++) { m_i[qq] = -1e30f; l_i[qq] = 0.f; o0[qq] = 0.f; o1[qq] = 0.f; }

    const int q0 = w * 8;

    for (int kb = 0; kb < S_; kb += 64) {
        __syncthreads();
        for (int e = tid; e < 4096; e += 256) {          // K chunk, transposed
            int j = e >> 6, d = e & 63;
            ks[d*65 + j] = Kp[(size_t)(kb + j)*64 + d];
        }
        {   // V chunk (contiguous)
            const float4* src = reinterpret_cast<const float4*>(Vp + (size_t)kb * 64);
            float4* dst = reinterpret_cast<float4*>(vs);
            for (int i = tid; i < 1024; i += 256) dst[i] = src[i];
        }
        __syncthreads();

        float s0[8], s1[8];
#pragma unroll
        for (int qq = 0; qq < 8; qq++) { s0[qq] = 0.f; s1[qq] = 0.f; }
#pragma unroll 16
        for (int d = 0; d < 64; d++) {
            float k0 = ks[d*65 + lane];
            float k1 = ks[d*65 + lane + 32];
#pragma unroll
            for (int qq = 0; qq < 8; qq++) {
                float qd = q_sh[(q0 + qq)*64 + d];
                s0[qq] += qd * k0;
                s1[qq] += qd * k1;
            }
        }
#pragma unroll
        for (int qq = 0; qq < 8; qq++) {
            float a0 = s0[qq] * 0.125f + hb;
            float a1 = s1[qq] * 0.125f + hb;
            float mx = fmaxf(a0, a1);
#pragma unroll
            for (int off = 16; off; off >>= 1)
                mx = fmaxf(mx, __shfl_xor_sync(0xffffffffu, mx, off));
            float mnew  = fmaxf(m_i[qq], mx);
            float scale = __expf(m_i[qq] - mnew);
            float p0 = __expf(a0 - mnew);
            float p1 = __expf(a1 - mnew);
            float ps = p0 + p1;
#pragma unroll
            for (int off = 16; off; off >>= 1)
                ps += __shfl_xor_sync(0xffffffffu, ps, off);
            l_i[qq] = l_i[qq] * scale + ps;
            o0[qq] *= scale;
            o1[qq] *= scale;
            m_i[qq] = mnew;
            p_sh[(q0 + qq)*64 + lane     ] = p0;
            p_sh[(q0 + qq)*64 + lane + 32] = p1;
        }
        __syncwarp();
#pragma unroll 16
        for (int j = 0; j < 64; j++) {
            float v0 = vs[j*64 + lane];
            float v1 = vs[j*64 + lane + 32];
#pragma unroll
            for (int qq = 0; qq < 8; qq++) {
                float pj = p_sh[(q0 + qq)*64 + j];
                o0[qq] += pj * v0;
                o1[qq] += pj * v1;
            }
        }
    }

    // write ctx in [b, s, h*64+d] layout (row-major 512) for the Wo GEMM
#pragma unroll
    for (int qq = 0; qq < 8; qq++) {
        float rl = 1.0f / l_i[qq];
        int srow = qb + q0 + qq;
        float* cp = ctx + ((size_t)(b*S_ + srow))*M_ + h*64;
        cp[lane     ] = o0[qq] * rl;
        cp[lane + 32] = o1[qq] * rl;
    }
}

// ---------------- layernorm ------------------------------------------------
__global__ __launch_bounds__(256)
void layernorm_k(const float* __restrict__ x, const float* __restrict__ g,
                 const float* __restrict__ bb, float* __restrict__ out)
{
    __shared__ float red[8];
    const int row = blockIdx.x, tid = threadIdx.x;
    const float4 v = reinterpret_cast<const float4*>(x + (size_t)row*1024)[tid];

    float s = v.x + v.y + v.z + v.w;
#pragma unroll
    for (int off = 16; off; off >>= 1) s += __shfl_xor_sync(0xffffffffu, s, off);
    if ((tid & 31) == 0) red[tid >> 5] = s;
    __syncthreads();
    if (tid < 32) {
        float t = (tid < 8) ? red[tid] : 0.f;
#pragma unroll
        for (int off = 4; off; off >>= 1) t += __shfl_xor_sync(0xffffffffu, t, off);
        if (tid == 0) red[0] = t;
    }
    __syncthreads();
    const float mean = red[0] * (1.0f / 1024.0f);
    const float dx = v.x - mean, dy = v.y - mean, dz = v.z - mean, dw = v.w - mean;
    float ss = dx*dx + dy*dy + dz*dz + dw*dw;
    __syncthreads();   // done reading red[0]
#pragma unroll
    for (int off = 16; off; off >>= 1) ss += __shfl_xor_sync(0xffffffffu, ss, off);
    if ((tid & 31) == 0) red[tid >> 5] = ss;
    __syncthreads();
    if (tid < 32) {
        float t = (tid < 8) ? red[tid] : 0.f;
#pragma unroll
        for (int off = 4; off; off >>= 1) t += __shfl_xor_sync(0xffffffffu, t, off);
        if (tid == 0) red[0] = t;
    }
    __syncthreads();
    const float inv = rsqrtf(red[0] * (1.0f / 1024.0f) + 1e-5f);
    const int c = tid * 4;
    float4 o;
    o.x = dx * inv * g[c    ] + bb[c    ];
    o.y = dy * inv * g[c + 1] + bb[c + 1];
    o.z = dz * inv * g[c + 2] + bb[c + 2];
    o.w = dw * inv * g[c + 3] + bb[c + 3];
    reinterpret_cast<float4*>(out + (size_t)row*1024)[tid] = o;
}

// ---------------- launch ---------------------------------------------------
extern "C" void kernel_launch(void* const* d_in, const int* in_sizes, int n_in,
                              void* d_out, int out_size)
{
    const float* x     = (const float*)d_in[0];
    const float* W_enc = (const float*)d_in[1];
    const float* b_enc = (const float*)d_in[2];
    const float* Wq    = (const float*)d_in[3];
    const float* bq    = (const float*)d_in[4];
    const float* Wk    = (const float*)d_in[5];
    const float* bk    = (const float*)d_in[6];
    const float* Wv    = (const float*)d_in[7];
    const float* bv    = (const float*)d_in[8];
    const float* Wo    = (const float*)d_in[9];
    const float* bo    = (const float*)d_in[10];
    const float* ocr   = (const float*)d_in[11];
    const float* W1    = (const float*)d_in[12];
    const float* b1    = (const float*)d_in[13];
    const float* W2    = (const float*)d_in[14];
    const float* b2    = (const float*)d_in[15];
    const float* ln_g  = (const float*)d_in[16];
    const float* ln_b  = (const float*)d_in[17];
    float* out = (float*)d_out;

    float *mem, *q, *k, *v, *ctx, *att, *h1, *h2;
    cudaGetSymbolAddress((void**)&mem, g_mem);
    cudaGetSymbolAddress((void**)&q,   g_q);
    cudaGetSymbolAddress((void**)&k,   g_k);
    cudaGetSymbolAddress((void**)&v,   g_v);
    cudaGetSymbolAddress((void**)&ctx, g_ctx);
    cudaGetSymbolAddress((void**)&att, g_att);
    cudaGetSymbolAddress((void**)&h1,  g_h1);
    cudaGetSymbolAddress((void**)&h2,  g_h2);

    cudaFuncSetAttribute(attn_kernel, cudaFuncAttributeMaxDynamicSharedMemorySize, ATTN_SMEM);

    dim3 blk(256);
    // 1) mem = x @ W_enc + b_enc
    sgemm128<0><<<dim3(4, 64), blk>>>(x, W_enc, b_enc, mem, R_, M_, D_);
    // 2) q/k/v = mem @ W? + b?, scattered to [B,H,S,DK]
    sgemm128<1><<<dim3(4, 64), blk>>>(mem, Wq, bq, q, R_, M_, M_);
    sgemm128<1><<<dim3(4, 64), blk>>>(mem, Wk, bk, k, R_, M_, M_);
    sgemm128<1><<<dim3(4, 64), blk>>>(mem, Wv, bv, v, R_, M_, M_);
    // 3) attention -> ctx in [b,s,(h,d)] layout
    attn_kernel<<<dim3(S_/64, B_*H_), blk, ATTN_SMEM>>>(q, k, v, ocr, ctx);
    // 4) att = ctx @ Wo + bo
    sgemm128<0><<<dim3(4, 64), blk>>>(ctx, Wo, bo, att, R_, M_, M_);
    // 5) h1 = x @ W1[:1024] + b1 ; h1 = gelu(h1 + att @ W1[1024:])
    sgemm128<0><<<dim3(8, 64), blk>>>(x,   W1,              b1,      h1, R_, D_, D_);
    sgemm128<2><<<dim3(8, 64), blk>>>(att, W1 + 1024*1024,  nullptr, h1, R_, D_, M_);
    // 6) h2 = h1 @ W2 + b2
    sgemm128<0><<<dim3(8, 64), blk>>>(h1, W2, b2, h2, R_, D_, D_);
    // 7) out = layernorm(h2)
    layernorm_k<<<R_, blk>>>(h2, ln_g, ln_b, out);
}

// round 3
// speedup vs baseline: 1.3642x; 1.3642x over previous
#include <cuda_runtime.h>
#include <cuda_bf16.h>
#include <math.h>
#include <stdint.h>

#define B_  4
#define S_  2048
#define D_  1024
#define M_  512
#define H_  8
#define R_  (B_*S_)   // 8192 token rows

// ---------------- scratch (device globals: no allocation) ----------------
__device__ float g_mem [R_*M_];
__device__ float g_qkv [3*R_*M_];      // [3][B][H][S][64]
__device__ float g_ctx [R_*M_];
__device__ float g_att [R_*M_];
__device__ float g_h1  [R_*D_];
__device__ float g_h2  [R_*D_];
__device__ float g_bqkv[3*M_];
// transposed weights: [N][K] row-major
__device__ float g_wenc_t[M_*D_];
__device__ float g_wqkv_t[3*M_*M_];
__device__ float g_wo_t  [M_*M_];
__device__ float g_w1_t  [D_*(D_+M_)];
__device__ float g_w2_t  [D_*D_];

// ---------------- helpers ----------------
__device__ __forceinline__ uint32_t smem_u32(const void* p) {
    uint32_t a;
    asm("{ .reg .u64 t; cvta.to.shared.u64 t, %1; cvt.u32.u64 %0, t; }" : "=r"(a) : "l"(p));
    return a;
}
__device__ __forceinline__ uint32_t pack_bf16(__nv_bfloat16 a, __nv_bfloat16 b) {
    return (uint32_t)__bfloat16_as_ushort(a) | ((uint32_t)__bfloat16_as_ushort(b) << 16);
}
__device__ __forceinline__ void split2(float x, __nv_bfloat16& h, __nv_bfloat16& l) {
    h = __float2bfloat16(x);                       // rn
    l = __float2bfloat16(x - __bfloat162float(h)); // residual
}
__device__ __forceinline__ float gelu_exact(float v) {
    return 0.5f * v * (1.0f + erff(v * 0.70710678118654752440f));
}

#define LDSM4(r, addr) \
    asm volatile("ldmatrix.sync.aligned.m8n8.x4.shared.b16 {%0,%1,%2,%3}, [%4];" \
        : "=r"((r)[0]), "=r"((r)[1]), "=r"((r)[2]), "=r"((r)[3]) : "r"(addr))

__device__ __forceinline__ void mma_bf16(float* c, const uint32_t* a, uint32_t b0, uint32_t b1) {
    asm volatile("mma.sync.aligned.m16n8k16.row.col.f32.bf16.bf16.f32 "
        "{%0,%1,%2,%3}, {%4,%5,%6,%7}, {%8,%9}, {%0,%1,%2,%3};"
        : "+f"(c[0]), "+f"(c[1]), "+f"(c[2]), "+f"(c[3])
        : "r"(a[0]), "r"(a[1]), "r"(a[2]), "r"(a[3]), "r"(b0), "r"(b1));
}

// ---------------- weight transpose: in [K,N] -> out [N,K] ----------------
__global__ void transpose_k(const float* __restrict__ in, float* __restrict__ out,
                            int K, int N)
{
    __shared__ float t[32][33];
    const int kb = blockIdx.y * 32, nb = blockIdx.x * 32;
    const int x = threadIdx.x, y = threadIdx.y;  // 32 x 8
#pragma unroll
    for (int j = 0; j < 32; j += 8)
        t[y + j][x] = in[(size_t)(kb + y + j) * N + nb + x];
    __syncthreads();
#pragma unroll
    for (int j = 0; j < 32; j += 8)
        out[(size_t)(nb + y + j) * K + kb + x] = t[x][y + j];
}

// ---------------- 3xBF16 emulated-fp32 GEMM on mma.sync ------------------
// C[M,N] = A[M,K] @ Bt[N,K]^T (+bias / epilogue). Tile 128x128, BK=32.
// A may be split along K: rows use A1 (k < KA) then A2 (k >= KA).
// EPI 0: C = acc + bias
// EPI 1: QKV scatter: col -> tensor(col>>9), head((col>>9? col&511)>>6), d
// EPI 2: C = gelu(acc + bias)
#define PITCH 80                    // bytes per 32-bf16 row (+pad: conflict-free ldmatrix)
#define ABUF  (128*PITCH)           // 10240 B
#define STAGE_BYTES (4*ABUF)        // Ahi,Alo,Bhi,Blo
#define GEMM_SMEM (2*STAGE_BYTES)   // 81920 B

template<int EPI>
__global__ __launch_bounds__(256, 1)
void hgemm(const float* __restrict__ A1, int lda1, int KA,
           const float* __restrict__ A2, int lda2,
           const float* __restrict__ Bt, int ldb,
           const float* __restrict__ bias,
           float* __restrict__ C, int ldc, int K)
{
    extern __shared__ char sm_[];
    const uint32_t sb = smem_u32(sm_);
    const int tid = threadIdx.x, wid = tid >> 5, lane = tid & 31;
    const int bm = blockIdx.y * 128, bn = blockIdx.x * 128;
    const int m0 = (wid & 3) * 32, n0 = (wid >> 2) * 64;

    float acc[2][8][4];
#pragma unroll
    for (int i = 0; i < 2; i++)
#pragma unroll
        for (int j = 0; j < 8; j++)
#pragma unroll
            for (int t = 0; t < 4; t++) acc[i][j][t] = 0.f;

    float4 pa[4], pb[4];

    auto LOAD = [&](int c) {
        const int k0 = c * 32;
        const float* s; int ld;
        if (k0 < KA) { s = A1 + k0; ld = lda1; } else { s = A2 + (k0 - KA); ld = lda2; }
#pragma unroll
        for (int it = 0; it < 4; it++) {
            int idx = tid + it * 256;
            int r = idx >> 3, c4 = (idx & 7) << 2;
            pa[it] = *reinterpret_cast<const float4*>(s + (size_t)(bm + r) * ld + c4);
        }
#pragma unroll
        for (int it = 0; it < 4; it++) {
            int idx = tid + it * 256;
            int r = idx >> 3, c4 = (idx & 7) << 2;
            pb[it] = *reinterpret_cast<const float4*>(Bt + (size_t)(bn + r) * ldb + k0 + c4);
        }
    };

    auto STS = [&](int buf) {
        char* base = sm_ + buf * STAGE_BYTES;
#pragma unroll
        for (int it = 0; it < 4; it++) {
            int idx = tid + it * 256;
            int r = idx >> 3, c4 = (idx & 7) << 2;
            __nv_bfloat16 h0, h1, h2, h3, l0, l1, l2, l3;
            split2(pa[it].x, h0, l0); split2(pa[it].y, h1, l1);
            split2(pa[it].z, h2, l2); split2(pa[it].w, h3, l3);
            char* p = base + r * PITCH + c4 * 2;
            *reinterpret_cast<uint2*>(p)        = make_uint2(pack_bf16(h0, h1), pack_bf16(h2, h3));
            *reinterpret_cast<uint2*>(p + ABUF) = make_uint2(pack_bf16(l0, l1), pack_bf16(l2, l3));
            split2(pb[it].x, h0, l0); split2(pb[it].y, h1, l1);
            split2(pb[it].z, h2, l2); split2(pb[it].w, h3, l3);
            char* q = base + 2 * ABUF + r * PITCH + c4 * 2;
            *reinterpret_cast<uint2*>(q)        = make_uint2(pack_bf16(h0, h1), pack_bf16(h2, h3));
            *reinterpret_cast<uint2*>(q + ABUF) = make_uint2(pack_bf16(l0, l1), pack_bf16(l2, l3));
        }
    };

    const int i4 = lane >> 3, l7 = lane & 7;
    const uint32_t aoff = (uint32_t)((m0 + ((i4 & 1) << 3) + l7) * PITCH + ((i4 >> 1) << 4));
    const uint32_t boff = (uint32_t)((n0 + ((i4 & 1) << 3) + l7) * PITCH + ((i4 >> 1) << 4));

    auto MMA = [&](int buf) {
        const uint32_t baseA = sb + buf * STAGE_BYTES;
        const uint32_t baseB = baseA + 2 * ABUF;
#pragma unroll
        for (int ks = 0; ks < 2; ks++) {
            uint32_t ah[2][4], al[2][4], bh[4][4], bl[4][4];
#pragma unroll
            for (int mi = 0; mi < 2; mi++) {
                uint32_t ad = baseA + aoff + mi * (16 * PITCH) + ks * 32;
                LDSM4(ah[mi], ad);
                LDSM4(al[mi], ad + ABUF);
            }
#pragma unroll
            for (int nj = 0; nj < 4; nj++) {
                uint32_t bd = baseB + boff + nj * (16 * PITCH) + ks * 32;
                LDSM4(bh[nj], bd);
                LDSM4(bl[nj], bd + ABUF);
            }
#pragma unroll
            for (int mi = 0; mi < 2; mi++)
#pragma unroll
                for (int nj = 0; nj < 4; nj++) {
                    mma_bf16(acc[mi][nj*2],   ah[mi], bh[nj][0], bh[nj][2]);
                    mma_bf16(acc[mi][nj*2],   ah[mi], bl[nj][0], bl[nj][2]);
                    mma_bf16(acc[mi][nj*2],   al[mi], bh[nj][0], bh[nj][2]);
                    mma_bf16(acc[mi][nj*2+1], ah[mi], bh[nj][1], bh[nj][3]);
                    mma_bf16(acc[mi][nj*2+1], ah[mi], bl[nj][1], bl[nj][3]);
                    mma_bf16(acc[mi][nj*2+1], al[mi], bh[nj][1], bh[nj][3]);
                }
        }
    };

    const int NC = K >> 5;
    LOAD(0);
    STS(0);
    __syncthreads();
    for (int c = 0; c < NC; c++) {
        if (c + 1 < NC) LOAD(c + 1);
        MMA(c & 1);
        if (c + 1 < NC) STS((c + 1) & 1);
        __syncthreads();
    }

    // ---- epilogue ----
    const int g = lane >> 2, tig = lane & 3;
#pragma unroll
    for (int mi = 0; mi < 2; mi++) {
#pragma unroll
        for (int nf = 0; nf < 8; nf++) {
            const int col = bn + n0 + nf * 8 + tig * 2;
            const int r0  = bm + m0 + mi * 16 + g;
            float b0v = 0.f, b1v = 0.f;
            if (bias) { b0v = bias[col]; b1v = bias[col + 1]; }
            float v00 = acc[mi][nf][0] + b0v, v01 = acc[mi][nf][1] + b1v;
            float v10 = acc[mi][nf][2] + b0v, v11 = acc[mi][nf][3] + b1v;
            if (EPI == 2) {
                v00 = gelu_exact(v00); v01 = gelu_exact(v01);
                v10 = gelu_exact(v10); v11 = gelu_exact(v11);
            }
            if (EPI == 1) {
                const int tns = col >> 9, rem = col & 511;
                const int h = rem >> 6, d = rem & 63;
                {
                    size_t o = ((((size_t)(tns * 4 + (r0 >> 11)) * 8 + h) * 2048 + (r0 & 2047)) * 64 + d);
                    *reinterpret_cast<float2*>(C + o) = make_float2(v00, v01);
                }
                {
                    const int r1 = r0 + 8;
                    size_t o = ((((size_t)(tns * 4 + (r1 >> 11)) * 8 + h) * 2048 + (r1 & 2047)) * 64 + d);
                    *reinterpret_cast<float2*>(C + o) = make_float2(v10, v11);
                }
            } else {
                *reinterpret_cast<float2*>(C + (size_t)r0 * ldc + col)       = make_float2(v00, v01);
                *reinterpret_cast<float2*>(C + (size_t)(r0 + 8) * ldc + col) = make_float2(v10, v11);
            }
        }
    }
}

// ---------------- flash attention (fp32, online softmax) -----------------
#define ATTN_SMEM ((64*64 + 64*65 + 64*64 + 64*64) * 4)

__global__ __launch_bounds__(256)
void attn_kernel(const float* __restrict__ Qg, const float* __restrict__ Kg,
                 const float* __restrict__ Vg, const float* __restrict__ ocr,
                 float* __restrict__ ctx)
{
    extern __shared__ float sm[];
    float* q_sh = sm;
    float* ks   = sm + 4096;
    float* vs   = sm + 4096 + 4160;
    float* p_sh = sm + 4096 + 4160 + 4096;

    const int tid  = threadIdx.x;
    const int w    = tid >> 5, lane = tid & 31;
    const int bh   = blockIdx.y;
    const int b    = bh >> 3, h = bh & 7;
    const int qb   = blockIdx.x * 64;
    const float hb = ocr[h];

    const float* Qp = Qg + (size_t)bh * S_ * 64;
    const float* Kp = Kg + (size_t)bh * S_ * 64;
    const float* Vp = Vg + (size_t)bh * S_ * 64;

    {
        const float4* src = reinterpret_cast<const float4*>(Qp + (size_t)qb * 64);
        float4* dst = reinterpret_cast<float4*>(q_sh);
        for (int i = tid; i < 1024; i += 256) dst[i] = src[i];
    }

    float m_i[8], l_i[8], o0[8], o1[8];
#pragma unroll
    for (int qq = 0; qq < 8; qq++) { m_i[qq] = -1e30f; l_i[qq] = 0.f; o0[qq] = 0.f; o1[qq] = 0.f; }

    const int q0 = w * 8;

    for (int kb = 0; kb < S_; kb += 64) {
        __syncthreads();
        for (int e = tid; e < 4096; e += 256) {
            int j = e >> 6, d = e & 63;
            ks[d*65 + j] = Kp[(size_t)(kb + j)*64 + d];
        }
        {
            const float4* src = reinterpret_cast<const float4*>(Vp + (size_t)kb * 64);
            float4* dst = reinterpret_cast<float4*>(vs);
            for (int i = tid; i < 1024; i += 256) dst[i] = src[i];
        }
        __syncthreads();

        float s0[8], s1[8];
#pragma unroll
        for (int qq = 0; qq < 8; qq++) { s0[qq] = 0.f; s1[qq] = 0.f; }
#pragma unroll 16
        for (int d = 0; d < 64; d++) {
            float k0 = ks[d*65 + lane];
            float k1 = ks[d*65 + lane + 32];
#pragma unroll
            for (int qq = 0; qq < 8; qq++) {
                float qd = q_sh[(q0 + qq)*64 + d];
                s0[qq] += qd * k0;
                s1[qq] += qd * k1;
            }
        }
#pragma unroll
        for (int qq = 0; qq < 8; qq++) {
            float a0 = s0[qq] * 0.125f + hb;
            float a1 = s1[qq] * 0.125f + hb;
            float mx = fmaxf(a0, a1);
#pragma unroll
            for (int off = 16; off; off >>= 1)
                mx = fmaxf(mx, __shfl_xor_sync(0xffffffffu, mx, off));
            float mnew  = fmaxf(m_i[qq], mx);
            float scale = __expf(m_i[qq] - mnew);
            float p0 = __expf(a0 - mnew);
            float p1 = __expf(a1 - mnew);
            float ps = p0 + p1;
#pragma unroll
            for (int off = 16; off; off >>= 1)
                ps += __shfl_xor_sync(0xffffffffu, ps, off);
            l_i[qq] = l_i[qq] * scale + ps;
            o0[qq] *= scale;
            o1[qq] *= scale;
            m_i[qq] = mnew;
            p_sh[(q0 + qq)*64 + lane     ] = p0;
            p_sh[(q0 + qq)*64 + lane + 32] = p1;
        }
        __syncwarp();
#pragma unroll 16
        for (int j = 0; j < 64; j++) {
            float v0 = vs[j*64 + lane];
            float v1 = vs[j*64 + lane + 32];
#pragma unroll
            for (int qq = 0; qq < 8; qq++) {
                float pj = p_sh[(q0 + qq)*64 + j];
                o0[qq] += pj * v0;
                o1[qq] += pj * v1;
            }
        }
    }

#pragma unroll
    for (int qq = 0; qq < 8; qq++) {
        float rl = 1.0f / l_i[qq];
        int srow = qb + q0 + qq;
        float* cp = ctx + ((size_t)(b*S_ + srow))*M_ + h*64;
        cp[lane     ] = o0[qq] * rl;
        cp[lane + 32] = o1[qq] * rl;
    }
}

// ---------------- layernorm ------------------------------------------------
__global__ __launch_bounds__(256)
void layernorm_k(const float* __restrict__ x, const float* __restrict__ g,
                 const float* __restrict__ bb, float* __restrict__ out)
{
    __shared__ float red[8];
    const int row = blockIdx.x, tid = threadIdx.x;
    const float4 v = reinterpret_cast<const float4*>(x + (size_t)row*1024)[tid];

    float s = v.x + v.y + v.z + v.w;
#pragma unroll
    for (int off = 16; off; off >>= 1) s += __shfl_xor_sync(0xffffffffu, s, off);
    if ((tid & 31) == 0) red[tid >> 5] = s;
    __syncthreads();
    if (tid < 32) {
        float t = (tid < 8) ? red[tid] : 0.f;
#pragma unroll
        for (int off = 4; off; off >>= 1) t += __shfl_xor_sync(0xffffffffu, t, off);
        if (tid == 0) red[0] = t;
    }
    __syncthreads();
    const float mean = red[0] * (1.0f / 1024.0f);
    const float dx = v.x - mean, dy = v.y - mean, dz = v.z - mean, dw = v.w - mean;
    float ss = dx*dx + dy*dy + dz*dz + dw*dw;
    __syncthreads();
#pragma unroll
    for (int off = 16; off; off >>= 1) ss += __shfl_xor_sync(0xffffffffu, ss, off);
    if ((tid & 31) == 0) red[tid >> 5] = ss;
    __syncthreads();
    if (tid < 32) {
        float t = (tid < 8) ? red[tid] : 0.f;
#pragma unroll
        for (int off = 4; off; off >>= 1) t += __shfl_xor_sync(0xffffffffu, t, off);
        if (tid == 0) red[0] = t;
    }
    __syncthreads();
    const float inv = rsqrtf(red[0] * (1.0f / 1024.0f) + 1e-5f);
    const int c = tid * 4;
    float4 o;
    o.x = dx * inv * g[c    ] + bb[c    ];
    o.y = dy * inv * g[c + 1] + bb[c + 1];
    o.z = dz * inv * g[c + 2] + bb[c + 2];
    o.w = dw * inv * g[c + 3] + bb[c + 3];
    reinterpret_cast<float4*>(out + (size_t)row*1024)[tid] = o;
}

// ---------------- launch ---------------------------------------------------
extern "C" void kernel_launch(void* const* d_in, const int* in_sizes, int n_in,
                              void* d_out, int out_size)
{
    const float* x     = (const float*)d_in[0];
    const float* W_enc = (const float*)d_in[1];
    const float* b_enc = (const float*)d_in[2];
    const float* Wq    = (const float*)d_in[3];
    const float* bq    = (const float*)d_in[4];
    const float* Wk    = (const float*)d_in[5];
    const float* bk    = (const float*)d_in[6];
    const float* Wv    = (const float*)d_in[7];
    const float* bv    = (const float*)d_in[8];
    const float* Wo    = (const float*)d_in[9];
    const float* bo    = (const float*)d_in[10];
    const float* ocr   = (const float*)d_in[11];
    const float* W1    = (const float*)d_in[12];
    const float* b1    = (const float*)d_in[13];
    const float* W2    = (const float*)d_in[14];
    const float* b2    = (const float*)d_in[15];
    const float* ln_g  = (const float*)d_in[16];
    const float* ln_b  = (const float*)d_in[17];
    float* out = (float*)d_out;

    float *mem, *qkv, *ctx, *att, *h1, *h2, *bqkv;
    float *wenc_t, *wqkv_t, *wo_t, *w1_t, *w2_t;
    cudaGetSymbolAddress((void**)&mem, g_mem);
    cudaGetSymbolAddress((void**)&qkv, g_qkv);
    cudaGetSymbolAddress((void**)&ctx, g_ctx);
    cudaGetSymbolAddress((void**)&att, g_att);
    cudaGetSymbolAddress((void**)&h1,  g_h1);
    cudaGetSymbolAddress((void**)&h2,  g_h2);
    cudaGetSymbolAddress((void**)&bqkv, g_bqkv);
    cudaGetSymbolAddress((void**)&wenc_t, g_wenc_t);
    cudaGetSymbolAddress((void**)&wqkv_t, g_wqkv_t);
    cudaGetSymbolAddress((void**)&wo_t, g_wo_t);
    cudaGetSymbolAddress((void**)&w1_t, g_w1_t);
    cudaGetSymbolAddress((void**)&w2_t, g_w2_t);

    cudaFuncSetAttribute(attn_kernel, cudaFuncAttributeMaxDynamicSharedMemorySize, ATTN_SMEM);
    cudaFuncSetAttribute(hgemm<0>, cudaFuncAttributeMaxDynamicSharedMemorySize, GEMM_SMEM);
    cudaFuncSetAttribute(hgemm<1>, cudaFuncAttributeMaxDynamicSharedMemorySize, GEMM_SMEM);
    cudaFuncSetAttribute(hgemm<2>, cudaFuncAttributeMaxDynamicSharedMemorySize, GEMM_SMEM);

    // concat qkv biases
    cudaMemcpyAsync(bqkv,        bq, M_ * sizeof(float), cudaMemcpyDeviceToDevice);
    cudaMemcpyAsync(bqkv + 512,  bk, M_ * sizeof(float), cudaMemcpyDeviceToDevice);
    cudaMemcpyAsync(bqkv + 1024, bv, M_ * sizeof(float), cudaMemcpyDeviceToDevice);

    dim3 tb(32, 8);
    // weight transposes (once per launch, cheap)
    transpose_k<<<dim3(M_/32, D_/32), tb>>>(W_enc, wenc_t, D_, M_);
    transpose_k<<<dim3(M_/32, M_/32), tb>>>(Wq, wqkv_t,             M_, M_);
    transpose_k<<<dim3(M_/32, M_/32), tb>>>(Wk, wqkv_t + 512*512,   M_, M_);
    transpose_k<<<dim3(M_/32, M_/32), tb>>>(Wv, wqkv_t + 2*512*512, M_, M_);
    transpose_k<<<dim3(M_/32, M_/32), tb>>>(Wo, wo_t, M_, M_);
    transpose_k<<<dim3(D_/32, (D_+M_)/32), tb>>>(W1, w1_t, D_+M_, D_);
    transpose_k<<<dim3(D_/32, D_/32), tb>>>(W2, w2_t, D_, D_);

    dim3 blk(256);
    // 1) mem = x @ W_enc + b_enc                     [8192,512], K=1024
    hgemm<0><<<dim3(4, 64), blk, GEMM_SMEM>>>(x, D_, D_, x, D_, wenc_t, D_, b_enc, mem, M_, D_);
    // 2) qkv = mem @ [Wq|Wk|Wv] + b  -> scatter [3][B,H,S,64]   N=1536, K=512
    hgemm<1><<<dim3(12, 64), blk, GEMM_SMEM>>>(mem, M_, M_, mem, M_, wqkv_t, M_, bqkv, qkv, 0, M_);
    // 3) attention -> ctx [b,s,(h,d)]
    attn_kernel<<<dim3(S_/64, B_*H_), blk, ATTN_SMEM>>>(qkv, qkv + (size_t)R_*M_,
                                                        qkv + 2*(size_t)R_*M_, ocr, ctx);
    // 4) att = ctx @ Wo + bo
    hgemm<0><<<dim3(4, 64), blk, GEMM_SMEM>>>(ctx, M_, M_, ctx, M_, wo_t, M_, bo, att, M_, M_);
    // 5) h1 = gelu(concat(x, att) @ W1 + b1)        N=1024, K=1536 (split A)
    hgemm<2><<<dim3(8, 64), blk, GEMM_SMEM>>>(x, D_, D_, att, M_, w1_t, D_+M_, b1, h1, D_, D_+M_);
    // 6) h2 = h1 @ W2 + b2
    hgemm<0><<<dim3(8, 64), blk, GEMM_SMEM>>>(h1, D_, D_, h1, D_, w2_t, D_, b2, h2, D_, D_);
    // 7) layernorm
    layernorm_k<<<R_, blk>>>(h2, ln_g, ln_b, out);
}

// round 4
// speedup vs baseline: 2.2462x; 1.6465x over previous
#include <cuda_runtime.h>
#include <cuda_bf16.h>
#include <math.h>
#include <stdint.h>

#define B_  4
#define S_  2048
#define D_  1024
#define M_  512
#define H_  8
#define R_  (B_*S_)   // 8192 token rows

// ---------------- scratch (device globals: no allocation) ----------------
// activation planes (bf16 hi/lo)
__device__ __nv_bfloat16 g_x_h [R_*D_],     g_x_l [R_*D_];
__device__ __nv_bfloat16 g_mem_h[R_*M_],    g_mem_l[R_*M_];
__device__ __nv_bfloat16 g_qkv_h[3*R_*M_],  g_qkv_l[3*R_*M_];   // [3][B][H][S][64]
__device__ __nv_bfloat16 g_ctx_h[R_*M_],    g_ctx_l[R_*M_];
__device__ __nv_bfloat16 g_att_h[R_*M_],    g_att_l[R_*M_];
__device__ __nv_bfloat16 g_h1_h [R_*D_],    g_h1_l [R_*D_];
__device__ float         g_h2  [R_*D_];
__device__ float         g_bqkv[3*M_];
// weight planes, transposed [N][K]
__device__ __nv_bfloat16 g_wenc_h[M_*D_],        g_wenc_l[M_*D_];
__device__ __nv_bfloat16 g_wqkv_h[3*M_*M_],      g_wqkv_l[3*M_*M_];
__device__ __nv_bfloat16 g_wo_h  [M_*M_],        g_wo_l  [M_*M_];
__device__ __nv_bfloat16 g_w1_h  [D_*(D_+M_)],   g_w1_l  [D_*(D_+M_)];
__device__ __nv_bfloat16 g_w2_h  [D_*D_],        g_w2_l  [D_*D_];

// ---------------- helpers ----------------
__device__ __forceinline__ uint32_t smem_u32(const void* p) {
    uint32_t a;
    asm("{ .reg .u64 t; cvta.to.shared.u64 t, %1; cvt.u32.u64 %0, t; }" : "=r"(a) : "l"(p));
    return a;
}
__device__ __forceinline__ uint32_t pack_bf16(__nv_bfloat16 a, __nv_bfloat16 b) {
    return (uint32_t)__bfloat16_as_ushort(a) | ((uint32_t)__bfloat16_as_ushort(b) << 16);
}
__device__ __forceinline__ void split2(float x, __nv_bfloat16& h, __nv_bfloat16& l) {
    h = __float2bfloat16(x);
    l = __float2bfloat16(x - __bfloat162float(h));
}
__device__ __forceinline__ void split_pack(float x, float y, uint32_t& hi, uint32_t& lo) {
    __nv_bfloat16 xh, xl, yh, yl;
    split2(x, xh, xl); split2(y, yh, yl);
    hi = pack_bf16(xh, yh); lo = pack_bf16(xl, yl);
}
__device__ __forceinline__ float gelu_exact(float v) {
    return 0.5f * v * (1.0f + erff(v * 0.70710678118654752440f));
}
__device__ __forceinline__ void cp16(uint32_t s, const void* g) {
    asm volatile("cp.async.cg.shared.global [%0], [%1], 16;" :: "r"(s), "l"(g) : "memory");
}
#define CP_COMMIT() asm volatile("cp.async.commit_group;" ::: "memory")
#define CP_WAIT0()  asm volatile("cp.async.wait_group 0;" ::: "memory")

#define LDSM4(r, addr) \
    asm volatile("ldmatrix.sync.aligned.m8n8.x4.shared.b16 {%0,%1,%2,%3}, [%4];" \
        : "=r"((r)[0]), "=r"((r)[1]), "=r"((r)[2]), "=r"((r)[3]) : "r"(addr))
#define LDSM4T(r, addr) \
    asm volatile("ldmatrix.sync.aligned.m8n8.x4.trans.shared.b16 {%0,%1,%2,%3}, [%4];" \
        : "=r"((r)[0]), "=r"((r)[1]), "=r"((r)[2]), "=r"((r)[3]) : "r"(addr))

__device__ __forceinline__ void mma_bf16(float* c, const uint32_t* a, uint32_t b0, uint32_t b1) {
    asm volatile("mma.sync.aligned.m16n8k16.row.col.f32.bf16.bf16.f32 "
        "{%0,%1,%2,%3}, {%4,%5,%6,%7}, {%8,%9}, {%0,%1,%2,%3};"
        : "+f"(c[0]), "+f"(c[1]), "+f"(c[2]), "+f"(c[3])
        : "r"(a[0]), "r"(a[1]), "r"(a[2]), "r"(a[3]), "r"(b0), "r"(b1));
}

// ---------------- prep: transpose + split ALL weights, concat qkv bias ----
__global__ void prep_w(const float* __restrict__ wenc, const float* __restrict__ wq,
                       const float* __restrict__ wk,   const float* __restrict__ wv,
                       const float* __restrict__ wo,   const float* __restrict__ w1,
                       const float* __restrict__ w2,
                       const float* __restrict__ bq, const float* __restrict__ bk,
                       const float* __restrict__ bv)
{
    __shared__ float t[32][33];
    int tw = blockIdx.x;
    const float* src; __nv_bfloat16 *dh, *dl; int K, N;
    if      (tw < 512)  {            src = wenc; dh = g_wenc_h; dl = g_wenc_l; K = 1024; N = 512; }
    else if (tw < 768)  { tw -= 512; src = wq; dh = g_wqkv_h;            dl = g_wqkv_l;            K = 512; N = 512; }
    else if (tw < 1024) { tw -= 768; src = wk; dh = g_wqkv_h + 512*512;  dl = g_wqkv_l + 512*512;  K = 512; N = 512; }
    else if (tw < 1280) { tw -= 1024; src = wv; dh = g_wqkv_h + 2*512*512; dl = g_wqkv_l + 2*512*512; K = 512; N = 512; }
    else if (tw < 1536) { tw -= 1280; src = wo; dh = g_wo_h; dl = g_wo_l; K = 512; N = 512; }
    else if (tw < 3072) { tw -= 1536; src = w1; dh = g_w1_h; dl = g_w1_l; K = 1536; N = 1024; }
    else                { tw -= 3072; src = w2; dh = g_w2_h; dl = g_w2_l; K = 1024; N = 1024; }

    const int tilesx = N / 32;
    const int kb = (tw / tilesx) * 32, nb = (tw % tilesx) * 32;
    const int x = threadIdx.x, y = threadIdx.y;  // 32 x 8
#pragma unroll
    for (int j = 0; j < 32; j += 8)
        t[y + j][x] = src[(size_t)(kb + y + j) * N + nb + x];
    __syncthreads();
#pragma unroll
    for (int j = 0; j < 32; j += 8) {
        float v = t[x][y + j];
        __nv_bfloat16 h, l; split2(v, h, l);
        size_t o = (size_t)(nb + y + j) * K + kb + x;
        dh[o] = h; dl[o] = l;
    }
    if (blockIdx.x == 0) {
        int tid = y * 32 + x;
        for (int i = tid; i < 1536; i += 256)
            g_bqkv[i] = (i < 512) ? bq[i] : (i < 1024) ? bk[i - 512] : bv[i - 1024];
    }
}

// ---------------- prep: split x into planes --------------------------------
__global__ void prep_x(const float* __restrict__ x)
{
    const size_t i = ((size_t)blockIdx.x * 256 + threadIdx.x) * 4;
    float4 v = *reinterpret_cast<const float4*>(x + i);
    __nv_bfloat16 h0,h1,h2,h3,l0,l1,l2,l3;
    split2(v.x,h0,l0); split2(v.y,h1,l1); split2(v.z,h2,l2); split2(v.w,h3,l3);
    *reinterpret_cast<uint2*>(g_x_h + i) = make_uint2(pack_bf16(h0,h1), pack_bf16(h2,h3));
    *reinterpret_cast<uint2*>(g_x_l + i) = make_uint2(pack_bf16(l0,l1), pack_bf16(l2,l3));
}

// ---------------- 3xBF16 GEMM from pre-split planes ------------------------
// C = A @ Bt^T. Tile 128x128, BK=32, 256 thr. A split along K at KA (A1|A2).
// EPI 0: planes out (o1=hi,o2=lo) += bias
// EPI 1: QKV scatter planes
// EPI 2: gelu(acc+bias) -> planes
// EPI 3: fp32 out (o1) + bias
#define PITCH 80
#define ABUF  (128*PITCH)           // 10240
#define STAGE_BYTES (4*ABUF)        // Ah,Al,Bh,Bl
#define GEMM_SMEM (2*STAGE_BYTES)   // 81920

template<int EPI>
__global__ __launch_bounds__(256, 1)
void hgemm(const __nv_bfloat16* __restrict__ A1h, const __nv_bfloat16* __restrict__ A1l,
           int lda1, int KA,
           const __nv_bfloat16* __restrict__ A2h, const __nv_bfloat16* __restrict__ A2l,
           int lda2,
           const __nv_bfloat16* __restrict__ Bh, const __nv_bfloat16* __restrict__ Bl,
           int ldb, const float* __restrict__ bias,
           void* __restrict__ o1, void* __restrict__ o2, int ldc, int K)
{
    extern __shared__ char sm_[];
    const uint32_t sb = smem_u32(sm_);
    const int tid = threadIdx.x, wid = tid >> 5, lane = tid & 31;
    const int bm = blockIdx.y * 128, bn = blockIdx.x * 128;
    const int m0 = (wid & 3) * 32, n0 = (wid >> 2) * 64;

    float acc[2][8][4];
#pragma unroll
    for (int i = 0; i < 2; i++)
#pragma unroll
        for (int j = 0; j < 8; j++)
#pragma unroll
            for (int t = 0; t < 4; t++) acc[i][j][t] = 0.f;

    auto LOADCP = [&](int c, int buf) {
        const int k0 = c * 32;
        const __nv_bfloat16 *ah, *al; int ld, ko;
        if (k0 < KA) { ah = A1h; al = A1l; ld = lda1; ko = k0; }
        else         { ah = A2h; al = A2l; ld = lda2; ko = k0 - KA; }
        const uint32_t st = sb + buf * STAGE_BYTES;
#pragma unroll
        for (int p = 0; p < 2; p++) {
            int idx = tid + p * 256;
            int r = idx >> 2, cc = (idx & 3) * 16;
            const char* s0 = (const char*)(ah + (size_t)(bm + r) * ld + ko) + cc;
            const char* s1 = (const char*)(al + (size_t)(bm + r) * ld + ko) + cc;
            cp16(st + r * PITCH + cc, s0);
            cp16(st + ABUF + r * PITCH + cc, s1);
        }
#pragma unroll
        for (int p = 0; p < 2; p++) {
            int idx = tid + p * 256;
            int r = idx >> 2, cc = (idx & 3) * 16;
            const char* s0 = (const char*)(Bh + (size_t)(bn + r) * ldb + k0) + cc;
            const char* s1 = (const char*)(Bl + (size_t)(bn + r) * ldb + k0) + cc;
            cp16(st + 2 * ABUF + r * PITCH + cc, s0);
            cp16(st + 3 * ABUF + r * PITCH + cc, s1);
        }
    };

    const int i4 = lane >> 3, l7 = lane & 7;
    const uint32_t aoff = (uint32_t)((m0 + ((i4 & 1) << 3) + l7) * PITCH + ((i4 >> 1) << 4));
    const uint32_t boff = (uint32_t)((n0 + ((i4 & 1) << 3) + l7) * PITCH + ((i4 >> 1) << 4));

    auto MMA = [&](int buf) {
        const uint32_t bA = sb + buf * STAGE_BYTES;
        const uint32_t bB = bA + 2 * ABUF;
#pragma unroll
        for (int ks = 0; ks < 2; ks++) {
            uint32_t ah[2][4], al[2][4], bh2[4][4], bl2[4][4];
#pragma unroll
            for (int mi = 0; mi < 2; mi++) {
                uint32_t ad = bA + aoff + mi * (16 * PITCH) + ks * 32;
                LDSM4(ah[mi], ad);
                LDSM4(al[mi], ad + ABUF);
            }
#pragma unroll
            for (int nj = 0; nj < 4; nj++) {
                uint32_t bd = bB + boff + nj * (16 * PITCH) + ks * 32;
                LDSM4(bh2[nj], bd);
                LDSM4(bl2[nj], bd + ABUF);
            }
#pragma unroll
            for (int mi = 0; mi < 2; mi++)
#pragma unroll
                for (int nj = 0; nj < 4; nj++) {
                    mma_bf16(acc[mi][nj*2],   ah[mi], bh2[nj][0], bh2[nj][2]);
                    mma_bf16(acc[mi][nj*2],   ah[mi], bl2[nj][0], bl2[nj][2]);
                    mma_bf16(acc[mi][nj*2],   al[mi], bh2[nj][0], bh2[nj][2]);
                    mma_bf16(acc[mi][nj*2+1], ah[mi], bh2[nj][1], bh2[nj][3]);
                    mma_bf16(acc[mi][nj*2+1], ah[mi], bl2[nj][1], bl2[nj][3]);
                    mma_bf16(acc[mi][nj*2+1], al[mi], bh2[nj][1], bh2[nj][3]);
                }
        }
    };

    const int NC = K >> 5;
    LOADCP(0, 0);
    CP_COMMIT();
    for (int c = 0; c < NC; c++) {
        CP_WAIT0();
        __syncthreads();
        if (c + 1 < NC) { LOADCP(c + 1, (c + 1) & 1); CP_COMMIT(); }
        MMA(c & 1);
    }

    // ---- epilogue ----
    const int g = lane >> 2, tig = lane & 3;
#pragma unroll
    for (int mi = 0; mi < 2; mi++) {
#pragma unroll
        for (int nf = 0; nf < 8; nf++) {
            const int col = bn + n0 + nf * 8 + tig * 2;
            const int r0  = bm + m0 + mi * 16 + g;
            const int r1  = r0 + 8;
            float b0v = bias ? bias[col] : 0.f;
            float b1v = bias ? bias[col + 1] : 0.f;
            float v00 = acc[mi][nf][0] + b0v, v01 = acc[mi][nf][1] + b1v;
            float v10 = acc[mi][nf][2] + b0v, v11 = acc[mi][nf][3] + b1v;
            if (EPI == 2) {
                v00 = gelu_exact(v00); v01 = gelu_exact(v01);
                v10 = gelu_exact(v10); v11 = gelu_exact(v11);
            }
            if (EPI == 3) {
                float* C = (float*)o1;
                *reinterpret_cast<float2*>(C + (size_t)r0 * ldc + col) = make_float2(v00, v01);
                *reinterpret_cast<float2*>(C + (size_t)r1 * ldc + col) = make_float2(v10, v11);
            } else {
                uint32_t h0, l0, h1, l1;
                split_pack(v00, v01, h0, l0);
                split_pack(v10, v11, h1, l1);
                __nv_bfloat16* Ch = (__nv_bfloat16*)o1;
                __nv_bfloat16* Cl = (__nv_bfloat16*)o2;
                if (EPI == 1) {
                    const int tns = col >> 9, rem = col & 511;
                    const int hh = rem >> 6, dd = rem & 63;
                    size_t oa = ((((size_t)(tns*4 + (r0 >> 11)) * 8 + hh) * 2048 + (r0 & 2047)) * 64 + dd);
                    size_t ob = ((((size_t)(tns*4 + (r1 >> 11)) * 8 + hh) * 2048 + (r1 & 2047)) * 64 + dd);
                    *reinterpret_cast<uint32_t*>(Ch + oa) = h0;
                    *reinterpret_cast<uint32_t*>(Cl + oa) = l0;
                    *reinterpret_cast<uint32_t*>(Ch + ob) = h1;
                    *reinterpret_cast<uint32_t*>(Cl + ob) = l1;
                } else {
                    *reinterpret_cast<uint32_t*>(Ch + (size_t)r0 * ldc + col) = h0;
                    *reinterpret_cast<uint32_t*>(Cl + (size_t)r0 * ldc + col) = l0;
                    *reinterpret_cast<uint32_t*>(Ch + (size_t)r1 * ldc + col) = h1;
                    *reinterpret_cast<uint32_t*>(Cl + (size_t)r1 * ldc + col) = l1;
                }
            }
        }
    }
}

// ---------------- tensor-core flash attention (3xbf16 emulated fp32) ------
// CTA: 128 thr (4 warps), 64 queries; loop over 32 key-chunks of 64.
// smem: Q hi/lo (pitch 144) + double-buffered K/V hi/lo.
#define AT_PITCH 144
#define AT_QBUF  (64*AT_PITCH)      // 9216
#define AT_STAGE (4*AT_QBUF)        // KH,KL,VH,VL = 36864
#define ATTN_SMEM (2*AT_QBUF + 2*AT_STAGE)  // 92160

__global__ __launch_bounds__(128, 2)
void attn_t(const __nv_bfloat16* __restrict__ qkvh, const __nv_bfloat16* __restrict__ qkvl,
            const float* __restrict__ ocr,
            __nv_bfloat16* __restrict__ ctxh, __nv_bfloat16* __restrict__ ctxl)
{
    extern __shared__ char sm_[];
    const uint32_t sb = smem_u32(sm_);
    const int tid = threadIdx.x, wid = tid >> 5, lane = tid & 31;
    const int bh = blockIdx.y;
    const int b = bh >> 3, h = bh & 7;
    const int qb = blockIdx.x * 64;
    const float hb = ocr[h];

    const size_t base = (size_t)bh * S_ * 64;   // elements within one tensor section
    const size_t ksec = (size_t)R_ * M_;        // k plane offset
    const size_t vsec = 2 * ksec;

    // Q load (8KB per plane)
#pragma unroll
    for (int i = 0; i < 4; i++) {
        int idx = tid + i * 128;
        int r = idx >> 3, cc = (idx & 7) * 16;
        const char* sh = (const char*)(qkvh + base + (size_t)(qb + r) * 64) + cc;
        const char* sl = (const char*)(qkvl + base + (size_t)(qb + r) * 64) + cc;
        cp16(sb + r * AT_PITCH + cc, sh);
        cp16(sb + AT_QBUF + r * AT_PITCH + cc, sl);
    }

    auto LOADKV = [&](int c, int buf) {
        const int kb = c * 64;
        const uint32_t st = sb + 2 * AT_QBUF + buf * AT_STAGE;
#pragma unroll
        for (int i = 0; i < 4; i++) {
            int idx = tid + i * 128;
            int r = idx >> 3, cc = (idx & 7) * 16;
            size_t go = base + (size_t)(kb + r) * 64;
            cp16(st + r * AT_PITCH + cc,                 (const char*)(qkvh + ksec + go) + cc);
            cp16(st + AT_QBUF + r * AT_PITCH + cc,       (const char*)(qkvl + ksec + go) + cc);
            cp16(st + 2 * AT_QBUF + r * AT_PITCH + cc,   (const char*)(qkvh + vsec + go) + cc);
            cp16(st + 3 * AT_QBUF + r * AT_PITCH + cc,   (const char*)(qkvl + vsec + go) + cc);
        }
    };

    LOADKV(0, 0);
    CP_COMMIT();

    const int q0 = wid * 16;
    const int i4 = lane >> 3, l7 = lane & 7;
    const int g = lane >> 2, tig = lane & 3;
    const uint32_t aoff = (uint32_t)((q0 + ((i4 & 1) << 3) + l7) * AT_PITCH + ((i4 >> 1) << 4));
    // V trans-ldmatrix lane addressing components
    const int vrow = ((lane >> 4) & 1) * 8 + (lane & 7);
    const int vcol = ((lane >> 3) & 1) * 8;

    float m0r = -1e30f, m1r = -1e30f, l0r = 0.f, l1r = 0.f;
    float o[8][4];
#pragma unroll
    for (int j = 0; j < 8; j++)
#pragma unroll
        for (int t = 0; t < 4; t++) o[j][t] = 0.f;

    for (int c = 0; c < 32; c++) {
        CP_WAIT0();
        __syncthreads();
        if (c + 1 < 32) { LOADKV(c + 1, (c + 1) & 1); CP_COMMIT(); }

        const uint32_t st = sb + 2 * AT_QBUF + (c & 1) * AT_STAGE;

        // ---- scores = Q @ K^T (3-term) ----
        float s[8][4];
#pragma unroll
        for (int j = 0; j < 8; j++)
#pragma unroll
            for (int t = 0; t < 4; t++) s[j][t] = 0.f;
#pragma unroll
        for (int ks = 0; ks < 4; ks++) {
            uint32_t qh2[4], ql2[4];
            LDSM4(qh2, sb + aoff + ks * 32);
            LDSM4(ql2, sb + AT_QBUF + aoff + ks * 32);
#pragma unroll
            for (int nj = 0; nj < 4; nj++) {
                uint32_t kh2[4], kl2[4];
                uint32_t bd = st + (nj * 16 + ((i4 & 1) << 3) + l7) * AT_PITCH + ((i4 >> 1) << 4) + ks * 32;
                LDSM4(kh2, bd);
                LDSM4(kl2, bd + AT_QBUF);
                mma_bf16(s[nj*2],   qh2, kh2[0], kh2[2]);
                mma_bf16(s[nj*2],   qh2, kl2[0], kl2[2]);
                mma_bf16(s[nj*2],   ql2, kh2[0], kh2[2]);
                mma_bf16(s[nj*2+1], qh2, kh2[1], kh2[3]);
                mma_bf16(s[nj*2+1], qh2, kl2[1], kl2[3]);
                mma_bf16(s[nj*2+1], ql2, kh2[1], kh2[3]);
            }
        }

        // ---- online softmax ----
        float mx0 = -1e30f, mx1 = -1e30f;
#pragma unroll
        for (int j = 0; j < 8; j++) {
            s[j][0] = s[j][0] * 0.125f + hb;
            s[j][1] = s[j][1] * 0.125f + hb;
            s[j][2] = s[j][2] * 0.125f + hb;
            s[j][3] = s[j][3] * 0.125f + hb;
            mx0 = fmaxf(mx0, fmaxf(s[j][0], s[j][1]));
            mx1 = fmaxf(mx1, fmaxf(s[j][2], s[j][3]));
        }
        mx0 = fmaxf(mx0, __shfl_xor_sync(0xffffffffu, mx0, 1));
        mx0 = fmaxf(mx0, __shfl_xor_sync(0xffffffffu, mx0, 2));
        mx1 = fmaxf(mx1, __shfl_xor_sync(0xffffffffu, mx1, 1));
        mx1 = fmaxf(mx1, __shfl_xor_sync(0xffffffffu, mx1, 2));
        const float mn0 = fmaxf(m0r, mx0), mn1 = fmaxf(m1r, mx1);
        const float sc0 = __expf(m0r - mn0), sc1 = __expf(m1r - mn1);
        float rs0 = 0.f, rs1 = 0.f;
#pragma unroll
        for (int j = 0; j < 8; j++) {
            s[j][0] = __expf(s[j][0] - mn0);
            s[j][1] = __expf(s[j][1] - mn0);
            s[j][2] = __expf(s[j][2] - mn1);
            s[j][3] = __expf(s[j][3] - mn1);
            rs0 += s[j][0] + s[j][1];
            rs1 += s[j][2] + s[j][3];
        }
        rs0 += __shfl_xor_sync(0xffffffffu, rs0, 1);
        rs0 += __shfl_xor_sync(0xffffffffu, rs0, 2);
        rs1 += __shfl_xor_sync(0xffffffffu, rs1, 1);
        rs1 += __shfl_xor_sync(0xffffffffu, rs1, 2);
        l0r = l0r * sc0 + rs0;
        l1r = l1r * sc1 + rs1;
        m0r = mn0; m1r = mn1;
#pragma unroll
        for (int j = 0; j < 8; j++) {
            o[j][0] *= sc0; o[j][1] *= sc0;
            o[j][2] *= sc1; o[j][3] *= sc1;
        }

        // ---- ctx += P @ V (3-term, P from score frags) ----
#pragma unroll
        for (int ks = 0; ks < 4; ks++) {
            uint32_t pa_h[4], pa_l[4];
            split_pack(s[2*ks][0],   s[2*ks][1],   pa_h[0], pa_l[0]);
            split_pack(s[2*ks][2],   s[2*ks][3],   pa_h[1], pa_l[1]);
            split_pack(s[2*ks+1][0], s[2*ks+1][1], pa_h[2], pa_l[2]);
            split_pack(s[2*ks+1][2], s[2*ks+1][3], pa_h[3], pa_l[3]);
#pragma unroll
            for (int d0 = 0; d0 < 4; d0++) {   // d base = d0*16, covers d-tiles 2d0, 2d0+1
                uint32_t vad = st + 2 * AT_QBUF +
                               (16 * ks + vrow) * AT_PITCH + (d0 * 16 + vcol) * 2;
                uint32_t vh2[4], vl2[4];
                LDSM4T(vh2, vad);
                LDSM4T(vl2, vad + AT_QBUF);
                const int dj = d0 * 2;
                mma_bf16(o[dj],   pa_h, vh2[0], vh2[2]);
                mma_bf16(o[dj],   pa_h, vl2[0], vl2[2]);
                mma_bf16(o[dj],   pa_l, vh2[0], vh2[2]);
                mma_bf16(o[dj+1], pa_h, vh2[1], vh2[3]);
                mma_bf16(o[dj+1], pa_h, vl2[1], vl2[3]);
                mma_bf16(o[dj+1], pa_l, vh2[1], vh2[3]);
            }
        }
    }

    // ---- write ctx planes [b, s, h*64+d] ----
    const float rl0 = 1.0f / l0r, rl1 = 1.0f / l1r;
    const int row0 = b * S_ + qb + q0 + g;
    const int row1 = row0 + 8;
#pragma unroll
    for (int j = 0; j < 8; j++) {
        const int col = h * 64 + j * 8 + tig * 2;
        uint32_t h0, l0, h1, l1;
        split_pack(o[j][0] * rl0, o[j][1] * rl0, h0, l0);
        split_pack(o[j][2] * rl1, o[j][3] * rl1, h1, l1);
        *reinterpret_cast<uint32_t*>(ctxh + (size_t)row0 * M_ + col) = h0;
        *reinterpret_cast<uint32_t*>(ctxl + (size_t)row0 * M_ + col) = l0;
        *reinterpret_cast<uint32_t*>(ctxh + (size_t)row1 * M_ + col) = h1;
        *reinterpret_cast<uint32_t*>(ctxl + (size_t)row1 * M_ + col) = l1;
    }
}

// ---------------- layernorm ------------------------------------------------
__global__ __launch_bounds__(256)
void layernorm_k(const float* __restrict__ x, const float* __restrict__ g,
                 const float* __restrict__ bb, float* __restrict__ out)
{
    __shared__ float red[8];
    const int row = blockIdx.x, tid = threadIdx.x;
    const float4 v = reinterpret_cast<const float4*>(x + (size_t)row*1024)[tid];

    float s = v.x + v.y + v.z + v.w;
#pragma unroll
    for (int off = 16; off; off >>= 1) s += __shfl_xor_sync(0xffffffffu, s, off);
    if ((tid & 31) == 0) red[tid >> 5] = s;
    __syncthreads();
    if (tid < 32) {
        float t = (tid < 8) ? red[tid] : 0.f;
#pragma unroll
        for (int off = 4; off; off >>= 1) t += __shfl_xor_sync(0xffffffffu, t, off);
        if (tid == 0) red[0] = t;
    }
    __syncthreads();
    const float mean = red[0] * (1.0f / 1024.0f);
    const float dx = v.x - mean, dy = v.y - mean, dz = v.z - mean, dw = v.w - mean;
    float ss = dx*dx + dy*dy + dz*dz + dw*dw;
    __syncthreads();
#pragma unroll
    for (int off = 16; off; off >>= 1) ss += __shfl_xor_sync(0xffffffffu, ss, off);
    if ((tid & 31) == 0) red[tid >> 5] = ss;
    __syncthreads();
    if (tid < 32) {
        float t = (tid < 8) ? red[tid] : 0.f;
#pragma unroll
        for (int off = 4; off; off >>= 1) t += __shfl_xor_sync(0xffffffffu, t, off);
        if (tid == 0) red[0] = t;
    }
    __syncthreads();
    const float inv = rsqrtf(red[0] * (1.0f / 1024.0f) + 1e-5f);
    const int c = tid * 4;
    float4 o;
    o.x = dx * inv * g[c    ] + bb[c    ];
    o.y = dy * inv * g[c + 1] + bb[c + 1];
    o.z = dz * inv * g[c + 2] + bb[c + 2];
    o.w = dw * inv * g[c + 3] + bb[c + 3];
    reinterpret_cast<float4*>(out + (size_t)row*1024)[tid] = o;
}

// ---------------- launch ---------------------------------------------------
extern "C" void kernel_launch(void* const* d_in, const int* in_sizes, int n_in,
                              void* d_out, int out_size)
{
    const float* x     = (const float*)d_in[0];
    const float* W_enc = (const float*)d_in[1];
    const float* b_enc = (const float*)d_in[2];
    const float* Wq    = (const float*)d_in[3];
    const float* bq    = (const float*)d_in[4];
    const float* Wk    = (const float*)d_in[5];
    const float* bk    = (const float*)d_in[6];
    const float* Wv    = (const float*)d_in[7];
    const float* bv    = (const float*)d_in[8];
    const float* Wo    = (const float*)d_in[9];
    const float* bo    = (const float*)d_in[10];
    const float* ocr   = (const float*)d_in[11];
    const float* W1    = (const float*)d_in[12];
    const float* b1    = (const float*)d_in[13];
    const float* W2    = (const float*)d_in[14];
    const float* b2    = (const float*)d_in[15];
    const float* ln_g  = (const float*)d_in[16];
    const float* ln_b  = (const float*)d_in[17];
    float* out = (float*)d_out;

    __nv_bfloat16 *xh, *xl, *memh, *meml, *qkvh, *qkvl, *ctxh, *ctxl, *atth, *attl, *h1h, *h1l;
    __nv_bfloat16 *wench, *wencl, *wqkvh, *wqkvl, *woh, *wol, *w1h, *w1l, *w2h, *w2l;
    float *h2, *bqkv;
    cudaGetSymbolAddress((void**)&xh, g_x_h);     cudaGetSymbolAddress((void**)&xl, g_x_l);
    cudaGetSymbolAddress((void**)&memh, g_mem_h); cudaGetSymbolAddress((void**)&meml, g_mem_l);
    cudaGetSymbolAddress((void**)&qkvh, g_qkv_h); cudaGetSymbolAddress((void**)&qkvl, g_qkv_l);
    cudaGetSymbolAddress((void**)&ctxh, g_ctx_h); cudaGetSymbolAddress((void**)&ctxl, g_ctx_l);
    cudaGetSymbolAddress((void**)&atth, g_att_h); cudaGetSymbolAddress((void**)&attl, g_att_l);
    cudaGetSymbolAddress((void**)&h1h, g_h1_h);   cudaGetSymbolAddress((void**)&h1l, g_h1_l);
    cudaGetSymbolAddress((void**)&h2, g_h2);      cudaGetSymbolAddress((void**)&bqkv, g_bqkv);
    cudaGetSymbolAddress((void**)&wench, g_wenc_h); cudaGetSymbolAddress((void**)&wencl, g_wenc_l);
    cudaGetSymbolAddress((void**)&wqkvh, g_wqkv_h); cudaGetSymbolAddress((void**)&wqkvl, g_wqkv_l);
    cudaGetSymbolAddress((void**)&woh, g_wo_h);   cudaGetSymbolAddress((void**)&wol, g_wo_l);
    cudaGetSymbolAddress((void**)&w1h, g_w1_h);   cudaGetSymbolAddress((void**)&w1l, g_w1_l);
    cudaGetSymbolAddress((void**)&w2h, g_w2_h);   cudaGetSymbolAddress((void**)&w2l, g_w2_l);

    cudaFuncSetAttribute(attn_t,   cudaFuncAttributeMaxDynamicSharedMemorySize, ATTN_SMEM);
    cudaFuncSetAttribute(hgemm<0>, cudaFuncAttributeMaxDynamicSharedMemorySize, GEMM_SMEM);
    cudaFuncSetAttribute(hgemm<1>, cudaFuncAttributeMaxDynamicSharedMemorySize, GEMM_SMEM);
    cudaFuncSetAttribute(hgemm<2>, cudaFuncAttributeMaxDynamicSharedMemorySize, GEMM_SMEM);
    cudaFuncSetAttribute(hgemm<3>, cudaFuncAttributeMaxDynamicSharedMemorySize, GEMM_SMEM);

    // 1) weight prep (transpose + split) + bias concat; x split
    prep_w<<<4096, dim3(32, 8)>>>(W_enc, Wq, Wk, Wv, Wo, W1, W2, bq, bk, bv);
    prep_x<<<8192, 256>>>(x);

    dim3 blk(256);
    // 2) mem = x @ W_enc + b_enc  -> planes          K=1024
    hgemm<0><<<dim3(4, 64), blk, GEMM_SMEM>>>(xh, xl, D_, D_, xh, xl, D_,
                                              wench, wencl, D_, b_enc, memh, meml, M_, D_);
    // 3) qkv = mem @ [Wq|Wk|Wv] + b -> scattered planes  N=1536, K=512
    hgemm<1><<<dim3(12, 64), blk, GEMM_SMEM>>>(memh, meml, M_, M_, memh, meml, M_,
                                               wqkvh, wqkvl, M_, bqkv, qkvh, qkvl, 0, M_);
    // 4) attention -> ctx planes
    attn_t<<<dim3(S_/64, B_*H_), 128, ATTN_SMEM>>>(qkvh, qkvl, ocr, ctxh, ctxl);
    // 5) att = ctx @ Wo + bo -> planes
    hgemm<0><<<dim3(4, 64), blk, GEMM_SMEM>>>(ctxh, ctxl, M_, M_, ctxh, ctxl, M_,
                                              woh, wol, M_, bo, atth, attl, M_, M_);
    // 6) h1 = gelu(concat(x, att) @ W1 + b1) -> planes   K=1536 (split A at 1024)
    hgemm<2><<<dim3(8, 64), blk, GEMM_SMEM>>>(xh, xl, D_, D_, atth, attl, M_,
                                              w1h, w1l, D_+M_, b1, h1h, h1l, D_, D_+M_);
    // 7) h2 = h1 @ W2 + b2 (fp32 out)
    hgemm<3><<<dim3(8, 64), blk, GEMM_SMEM>>>(h1h, h1l, D_, D_, h1h, h1l, D_,
                                              w2h, w2l, D_, b2, h2, nullptr, D_, D_);
    // 8) layernorm
    layernorm_k<<<R_, blk>>>(h2, ln_g, ln_b, out);
}

// round 5
// speedup vs baseline: 2.4297x; 1.0817x over previous
#include <cuda_runtime.h>
#include <cuda_bf16.h>
#include <math.h>
#include <stdint.h>

#define B_  4
#define S_  2048
#define D_  1024
#define M_  512
#define H_  8
#define R_  (B_*S_)   // 8192 token rows

// ---------------- scratch (device globals: no allocation) ----------------
__device__ __nv_bfloat16 g_x_h [R_*D_],     g_x_l [R_*D_];
__device__ __nv_bfloat16 g_mem_h[R_*M_],    g_mem_l[R_*M_];
__device__ __nv_bfloat16 g_qkv_h[3*R_*M_],  g_qkv_l[3*R_*M_];   // [3][B][H][S][64]
__device__ __nv_bfloat16 g_ctx_h[R_*M_],    g_ctx_l[R_*M_];
__device__ __nv_bfloat16 g_att_h[R_*M_],    g_att_l[R_*M_];
__device__ __nv_bfloat16 g_h1_h [R_*D_],    g_h1_l [R_*D_];
__device__ float         g_h2  [R_*D_];
__device__ float         g_bqkv[3*M_];
__device__ __nv_bfloat16 g_wenc_h[M_*D_],        g_wenc_l[M_*D_];
__device__ __nv_bfloat16 g_wqkv_h[3*M_*M_],      g_wqkv_l[3*M_*M_];
__device__ __nv_bfloat16 g_wo_h  [M_*M_],        g_wo_l  [M_*M_];
__device__ __nv_bfloat16 g_w1_h  [D_*(D_+M_)],   g_w1_l  [D_*(D_+M_)];
__device__ __nv_bfloat16 g_w2_h  [D_*D_],        g_w2_l  [D_*D_];

// ---------------- helpers ----------------
__device__ __forceinline__ uint32_t smem_u32(const void* p) {
    uint32_t a;
    asm("{ .reg .u64 t; cvta.to.shared.u64 t, %1; cvt.u32.u64 %0, t; }" : "=r"(a) : "l"(p));
    return a;
}
__device__ __forceinline__ uint32_t pack_bf16(__nv_bfloat16 a, __nv_bfloat16 b) {
    return (uint32_t)__bfloat16_as_ushort(a) | ((uint32_t)__bfloat16_as_ushort(b) << 16);
}
__device__ __forceinline__ void split2(float x, __nv_bfloat16& h, __nv_bfloat16& l) {
    h = __float2bfloat16(x);
    l = __float2bfloat16(x - __bfloat162float(h));
}
__device__ __forceinline__ void split_pack(float x, float y, uint32_t& hi, uint32_t& lo) {
    __nv_bfloat16 xh, xl, yh, yl;
    split2(x, xh, xl); split2(y, yh, yl);
    hi = pack_bf16(xh, yh); lo = pack_bf16(xl, yl);
}
__device__ __forceinline__ float gelu_exact(float v) {
    return 0.5f * v * (1.0f + erff(v * 0.70710678118654752440f));
}
__device__ __forceinline__ void cp16(uint32_t s, const void* g) {
    asm volatile("cp.async.cg.shared.global [%0], [%1], 16;" :: "r"(s), "l"(g) : "memory");
}
#define CP_COMMIT() asm volatile("cp.async.commit_group;" ::: "memory")
#define CP_WAIT0()  asm volatile("cp.async.wait_group 0;" ::: "memory")
#define CP_WAIT1()  asm volatile("cp.async.wait_group 1;" ::: "memory")

#define LDSM4(r, addr) \
    asm volatile("ldmatrix.sync.aligned.m8n8.x4.shared.b16 {%0,%1,%2,%3}, [%4];" \
        : "=r"((r)[0]), "=r"((r)[1]), "=r"((r)[2]), "=r"((r)[3]) : "r"(addr))
#define LDSM4T(r, addr) \
    asm volatile("ldmatrix.sync.aligned.m8n8.x4.trans.shared.b16 {%0,%1,%2,%3}, [%4];" \
        : "=r"((r)[0]), "=r"((r)[1]), "=r"((r)[2]), "=r"((r)[3]) : "r"(addr))

__device__ __forceinline__ void mma_bf16(float* c, const uint32_t* a, uint32_t b0, uint32_t b1) {
    asm volatile("mma.sync.aligned.m16n8k16.row.col.f32.bf16.bf16.f32 "
        "{%0,%1,%2,%3}, {%4,%5,%6,%7}, {%8,%9}, {%0,%1,%2,%3};"
        : "+f"(c[0]), "+f"(c[1]), "+f"(c[2]), "+f"(c[3])
        : "r"(a[0]), "r"(a[1]), "r"(a[2]), "r"(a[3]), "r"(b0), "r"(b1));
}

// ---------------- prep: transpose + split ALL weights, concat qkv bias ----
__global__ void prep_w(const float* __restrict__ wenc, const float* __restrict__ wq,
                       const float* __restrict__ wk,   const float* __restrict__ wv,
                       const float* __restrict__ wo,   const float* __restrict__ w1,
                       const float* __restrict__ w2,
                       const float* __restrict__ bq, const float* __restrict__ bk,
                       const float* __restrict__ bv)
{
    __shared__ float t[32][33];
    int tw = blockIdx.x;
    const float* src; __nv_bfloat16 *dh, *dl; int K, N;
    if      (tw < 512)  {            src = wenc; dh = g_wenc_h; dl = g_wenc_l; K = 1024; N = 512; }
    else if (tw < 768)  { tw -= 512; src = wq; dh = g_wqkv_h;            dl = g_wqkv_l;            K = 512; N = 512; }
    else if (tw < 1024) { tw -= 768; src = wk; dh = g_wqkv_h + 512*512;  dl = g_wqkv_l + 512*512;  K = 512; N = 512; }
    else if (tw < 1280) { tw -= 1024; src = wv; dh = g_wqkv_h + 2*512*512; dl = g_wqkv_l + 2*512*512; K = 512; N = 512; }
    else if (tw < 1536) { tw -= 1280; src = wo; dh = g_wo_h; dl = g_wo_l; K = 512; N = 512; }
    else if (tw < 3072) { tw -= 1536; src = w1; dh = g_w1_h; dl = g_w1_l; K = 1536; N = 1024; }
    else                { tw -= 3072; src = w2; dh = g_w2_h; dl = g_w2_l; K = 1024; N = 1024; }

    const int tilesx = N / 32;
    const int kb = (tw / tilesx) * 32, nb = (tw % tilesx) * 32;
    const int x = threadIdx.x, y = threadIdx.y;  // 32 x 8
#pragma unroll
    for (int j = 0; j < 32; j += 8)
        t[y + j][x] = src[(size_t)(kb + y + j) * N + nb + x];
    __syncthreads();
#pragma unroll
    for (int j = 0; j < 32; j += 8) {
        float v = t[x][y + j];
        __nv_bfloat16 h, l; split2(v, h, l);
        size_t o = (size_t)(nb + y + j) * K + kb + x;
        dh[o] = h; dl[o] = l;
    }
    if (blockIdx.x == 0) {
        int tid = y * 32 + x;
        for (int i = tid; i < 1536; i += 256)
            g_bqkv[i] = (i < 512) ? bq[i] : (i < 1024) ? bk[i - 512] : bv[i - 1024];
    }
}

// ---------------- prep: split x into planes --------------------------------
__global__ void prep_x(const float* __restrict__ x)
{
    const size_t i = ((size_t)blockIdx.x * 256 + threadIdx.x) * 4;
    float4 v = *reinterpret_cast<const float4*>(x + i);
    __nv_bfloat16 h0,h1,h2,h3,l0,l1,l2,l3;
    split2(v.x,h0,l0); split2(v.y,h1,l1); split2(v.z,h2,l2); split2(v.w,h3,l3);
    *reinterpret_cast<uint2*>(g_x_h + i) = make_uint2(pack_bf16(h0,h1), pack_bf16(h2,h3));
    *reinterpret_cast<uint2*>(g_x_l + i) = make_uint2(pack_bf16(l0,l1), pack_bf16(l2,l3));
}

// ---------------- 3xBF16 GEMM, BK=16, 3-stage ring, 2 CTAs/SM --------------
// C = A @ Bt^T. Tile 128x128, 256 thr, warp tile 32x64.
// EPI 0: planes out + bias; EPI 1: QKV scatter planes; EPI 2: gelu -> planes;
// EPI 3: fp32 out + bias
#define ABUF  4096                  // 128 rows x 32 B (16 bf16), swizzled
#define STAGE_BYTES (4*ABUF)        // Ah,Al,Bh,Bl = 16384
#define NSTAGE 3
#define GEMM_SMEM (NSTAGE*STAGE_BYTES)   // 49152

template<int EPI>
__global__ __launch_bounds__(256, 2)
void hgemm(const __nv_bfloat16* __restrict__ A1h, const __nv_bfloat16* __restrict__ A1l,
           int lda1, int KA,
           const __nv_bfloat16* __restrict__ A2h, const __nv_bfloat16* __restrict__ A2l,
           int lda2,
           const __nv_bfloat16* __restrict__ Bh, const __nv_bfloat16* __restrict__ Bl,
           int ldb, const float* __restrict__ bias,
           void* __restrict__ o1, void* __restrict__ o2, int ldc, int K)
{
    extern __shared__ char sm_[];
    const uint32_t sb = smem_u32(sm_);
    const int tid = threadIdx.x, wid = tid >> 5, lane = tid & 31;
    const int bm = blockIdx.y * 128, bn = blockIdx.x * 128;
    const int m0 = (wid & 3) * 32, n0 = (wid >> 2) * 64;

    float acc[2][8][4];
#pragma unroll
    for (int i = 0; i < 2; i++)
#pragma unroll
        for (int j = 0; j < 8; j++)
#pragma unroll
            for (int t = 0; t < 4; t++) acc[i][j][t] = 0.f;

    // per-thread cp.async slot: one 16B chunk per plane
    const int cr = tid >> 1, cc2 = tid & 1;
    const uint32_t cso = cr * 32 + ((cc2 ^ ((cr >> 2) & 1)) << 4);
    const int celem = cc2 * 8;

    auto LOADCP = [&](int c, int buf) {
        const int k0 = c * 16;
        const __nv_bfloat16 *ah, *al; int ld, ko;
        if (k0 < KA) { ah = A1h; al = A1l; ld = lda1; ko = k0; }
        else         { ah = A2h; al = A2l; ld = lda2; ko = k0 - KA; }
        const uint32_t st = sb + buf * STAGE_BYTES;
        cp16(st + cso,            ah + (size_t)(bm + cr) * ld + ko + celem);
        cp16(st + ABUF + cso,     al + (size_t)(bm + cr) * ld + ko + celem);
        cp16(st + 2*ABUF + cso,   Bh + (size_t)(bn + cr) * ldb + k0 + celem);
        cp16(st + 3*ABUF + cso,   Bl + (size_t)(bn + cr) * ldb + k0 + celem);
    };

    // ldmatrix lane offsets (constant across chunks)
    const int i4 = lane >> 3, l7 = lane & 7;
    const int khalf = i4 >> 1;
    uint32_t aoffs[2], boffs[4];
#pragma unroll
    for (int mi = 0; mi < 2; mi++) {
        int row = m0 + mi * 16 + ((i4 & 1) << 3) + l7;
        aoffs[mi] = row * 32 + ((khalf ^ ((row >> 2) & 1)) << 4);
    }
#pragma unroll
    for (int nj = 0; nj < 4; nj++) {
        int row = n0 + nj * 16 + ((i4 & 1) << 3) + l7;
        boffs[nj] = row * 32 + ((khalf ^ ((row >> 2) & 1)) << 4);
    }

    auto MMA = [&](int buf) {
        const uint32_t bA = sb + buf * STAGE_BYTES;
        const uint32_t bB = bA + 2 * ABUF;
        uint32_t ah2[2][4], al2[2][4];
#pragma unroll
        for (int mi = 0; mi < 2; mi++) {
            LDSM4(ah2[mi], bA + aoffs[mi]);
            LDSM4(al2[mi], bA + ABUF + aoffs[mi]);
        }
#pragma unroll
        for (int nj = 0; nj < 4; nj++) {
            uint32_t bh2[4], bl2[4];
            LDSM4(bh2, bB + boffs[nj]);
            LDSM4(bl2, bB + ABUF + boffs[nj]);
#pragma unroll
            for (int mi = 0; mi < 2; mi++) {
                mma_bf16(acc[mi][nj*2],   ah2[mi], bh2[0], bh2[2]);
                mma_bf16(acc[mi][nj*2+1], ah2[mi], bh2[1], bh2[3]);
                mma_bf16(acc[mi][nj*2],   ah2[mi], bl2[0], bl2[2]);
                mma_bf16(acc[mi][nj*2+1], ah2[mi], bl2[1], bl2[3]);
                mma_bf16(acc[mi][nj*2],   al2[mi], bh2[0], bh2[2]);
                mma_bf16(acc[mi][nj*2+1], al2[mi], bh2[1], bh2[3]);
            }
        }
    };

    const int NC = K >> 4;
    LOADCP(0, 0); CP_COMMIT();
    LOADCP(1, 1); CP_COMMIT();
    for (int c = 0; c < NC; c++) {
        CP_WAIT1();
        __syncthreads();
        if (c + 2 < NC) { LOADCP(c + 2, (c + 2) % 3); CP_COMMIT(); }
        MMA(c % 3);
    }

    // ---- epilogue ----
    const int g = lane >> 2, tig = lane & 3;
#pragma unroll
    for (int mi = 0; mi < 2; mi++) {
#pragma unroll
        for (int nf = 0; nf < 8; nf++) {
            const int col = bn + n0 + nf * 8 + tig * 2;
            const int r0  = bm + m0 + mi * 16 + g;
            const int r1  = r0 + 8;
            float b0v = bias ? bias[col] : 0.f;
            float b1v = bias ? bias[col + 1] : 0.f;
            float v00 = acc[mi][nf][0] + b0v, v01 = acc[mi][nf][1] + b1v;
            float v10 = acc[mi][nf][2] + b0v, v11 = acc[mi][nf][3] + b1v;
            if (EPI == 2) {
                v00 = gelu_exact(v00); v01 = gelu_exact(v01);
                v10 = gelu_exact(v10); v11 = gelu_exact(v11);
            }
            if (EPI == 3) {
                float* C = (float*)o1;
                *reinterpret_cast<float2*>(C + (size_t)r0 * ldc + col) = make_float2(v00, v01);
                *reinterpret_cast<float2*>(C + (size_t)r1 * ldc + col) = make_float2(v10, v11);
            } else {
                uint32_t h0, l0, h1, l1;
                split_pack(v00, v01, h0, l0);
                split_pack(v10, v11, h1, l1);
                __nv_bfloat16* Ch = (__nv_bfloat16*)o1;
                __nv_bfloat16* Cl = (__nv_bfloat16*)o2;
                if (EPI == 1) {
                    const int tns = col >> 9, rem = col & 511;
                    const int hh = rem >> 6, dd = rem & 63;
                    size_t oa = ((((size_t)(tns*4 + (r0 >> 11)) * 8 + hh) * 2048 + (r0 & 2047)) * 64 + dd);
                    size_t ob = ((((size_t)(tns*4 + (r1 >> 11)) * 8 + hh) * 2048 + (r1 & 2047)) * 64 + dd);
                    *reinterpret_cast<uint32_t*>(Ch + oa) = h0;
                    *reinterpret_cast<uint32_t*>(Cl + oa) = l0;
                    *reinterpret_cast<uint32_t*>(Ch + ob) = h1;
                    *reinterpret_cast<uint32_t*>(Cl + ob) = l1;
                } else {
                    *reinterpret_cast<uint32_t*>(Ch + (size_t)r0 * ldc + col) = h0;
                    *reinterpret_cast<uint32_t*>(Cl + (size_t)r0 * ldc + col) = l0;
                    *reinterpret_cast<uint32_t*>(Ch + (size_t)r1 * ldc + col) = h1;
                    *reinterpret_cast<uint32_t*>(Cl + (size_t)r1 * ldc + col) = l1;
                }
            }
        }
    }
}

// ---------------- tensor-core flash attention (3xbf16 emulated fp32) ------
#define AT_PITCH 144
#define AT_QBUF  (64*AT_PITCH)      // 9216
#define AT_STAGE (4*AT_QBUF)        // KH,KL,VH,VL = 36864
#define ATTN_SMEM (2*AT_QBUF + 2*AT_STAGE)  // 92160

__global__ __launch_bounds__(128, 2)
void attn_t(const __nv_bfloat16* __restrict__ qkvh, const __nv_bfloat16* __restrict__ qkvl,
            const float* __restrict__ ocr,
            __nv_bfloat16* __restrict__ ctxh, __nv_bfloat16* __restrict__ ctxl)
{
    extern __shared__ char sm_[];
    const uint32_t sb = smem_u32(sm_);
    const int tid = threadIdx.x, wid = tid >> 5, lane = tid & 31;
    const int bh = blockIdx.y;
    const int b = bh >> 3, h = bh & 7;
    const int qb = blockIdx.x * 64;
    const float hb = ocr[h];

    const size_t base = (size_t)bh * S_ * 64;
    const size_t ksec = (size_t)R_ * M_;
    const size_t vsec = 2 * ksec;

#pragma unroll
    for (int i = 0; i < 4; i++) {
        int idx = tid + i * 128;
        int r = idx >> 3, cc = (idx & 7) * 16;
        const char* sh = (const char*)(qkvh + base + (size_t)(qb + r) * 64) + cc;
        const char* sl = (const char*)(qkvl + base + (size_t)(qb + r) * 64) + cc;
        cp16(sb + r * AT_PITCH + cc, sh);
        cp16(sb + AT_QBUF + r * AT_PITCH + cc, sl);
    }

    auto LOADKV = [&](int c, int buf) {
        const int kb = c * 64;
        const uint32_t st = sb + 2 * AT_QBUF + buf * AT_STAGE;
#pragma unroll
        for (int i = 0; i < 4; i++) {
            int idx = tid + i * 128;
            int r = idx >> 3, cc = (idx & 7) * 16;
            size_t go = base + (size_t)(kb + r) * 64;
            cp16(st + r * AT_PITCH + cc,                 (const char*)(qkvh + ksec + go) + cc);
            cp16(st + AT_QBUF + r * AT_PITCH + cc,       (const char*)(qkvl + ksec + go) + cc);
            cp16(st + 2 * AT_QBUF + r * AT_PITCH + cc,   (const char*)(qkvh + vsec + go) + cc);
            cp16(st + 3 * AT_QBUF + r * AT_PITCH + cc,   (const char*)(qkvl + vsec + go) + cc);
        }
    };

    LOADKV(0, 0);
    CP_COMMIT();

    const int q0 = wid * 16;
    const int i4 = lane >> 3, l7 = lane & 7;
    const int g = lane >> 2, tig = lane & 3;
    const uint32_t aoff = (uint32_t)((q0 + ((i4 & 1) << 3) + l7) * AT_PITCH + ((i4 >> 1) << 4));
    const int vrow = ((lane >> 4) & 1) * 8 + (lane & 7);
    const int vcol = ((lane >> 3) & 1) * 8;

    float m0r = -1e30f, m1r = -1e30f, l0r = 0.f, l1r = 0.f;
    float o[8][4];
#pragma unroll
    for (int j = 0; j < 8; j++)
#pragma unroll
        for (int t = 0; t < 4; t++) o[j][t] = 0.f;

    for (int c = 0; c < 32; c++) {
        CP_WAIT0();
        __syncthreads();
        if (c + 1 < 32) { LOADKV(c + 1, (c + 1) & 1); CP_COMMIT(); }

        const uint32_t st = sb + 2 * AT_QBUF + (c & 1) * AT_STAGE;

        float s[8][4];
#pragma unroll
        for (int j = 0; j < 8; j++)
#pragma unroll
            for (int t = 0; t < 4; t++) s[j][t] = 0.f;
#pragma unroll
        for (int ks = 0; ks < 4; ks++) {
            uint32_t qh2[4], ql2[4];
            LDSM4(qh2, sb + aoff + ks * 32);
            LDSM4(ql2, sb + AT_QBUF + aoff + ks * 32);
#pragma unroll
            for (int nj = 0; nj < 4; nj++) {
                uint32_t kh2[4], kl2[4];
                uint32_t bd = st + (nj * 16 + ((i4 & 1) << 3) + l7) * AT_PITCH + ((i4 >> 1) << 4) + ks * 32;
                LDSM4(kh2, bd);
                LDSM4(kl2, bd + AT_QBUF);
                mma_bf16(s[nj*2],   qh2, kh2[0], kh2[2]);
                mma_bf16(s[nj*2],   qh2, kl2[0], kl2[2]);
                mma_bf16(s[nj*2],   ql2, kh2[0], kh2[2]);
                mma_bf16(s[nj*2+1], qh2, kh2[1], kh2[3]);
                mma_bf16(s[nj*2+1], qh2, kl2[1], kl2[3]);
                mma_bf16(s[nj*2+1], ql2, kh2[1], kh2[3]);
            }
        }

        float mx0 = -1e30f, mx1 = -1e30f;
#pragma unroll
        for (int j = 0; j < 8; j++) {
            s[j][0] = s[j][0] * 0.125f + hb;
            s[j][1] = s[j][1] * 0.125f + hb;
            s[j][2] = s[j][2] * 0.125f + hb;
            s[j][3] = s[j][3] * 0.125f + hb;
            mx0 = fmaxf(mx0, fmaxf(s[j][0], s[j][1]));
            mx1 = fmaxf(mx1, fmaxf(s[j][2], s[j][3]));
        }
        mx0 = fmaxf(mx0, __shfl_xor_sync(0xffffffffu, mx0, 1));
        mx0 = fmaxf(mx0, __shfl_xor_sync(0xffffffffu, mx0, 2));
        mx1 = fmaxf(mx1, __shfl_xor_sync(0xffffffffu, mx1, 1));
        mx1 = fmaxf(mx1, __shfl_xor_sync(0xffffffffu, mx1, 2));
        const float mn0 = fmaxf(m0r, mx0), mn1 = fmaxf(m1r, mx1);
        const float sc0 = __expf(m0r - mn0), sc1 = __expf(m1r - mn1);
        float rs0 = 0.f, rs1 = 0.f;
#pragma unroll
        for (int j = 0; j < 8; j++) {
            s[j][0] = __expf(s[j][0] - mn0);
            s[j][1] = __expf(s[j][1] - mn0);
            s[j][2] = __expf(s[j][2] - mn1);
            s[j][3] = __expf(s[j][3] - mn1);
            rs0 += s[j][0] + s[j][1];
            rs1 += s[j][2] + s[j][3];
        }
        rs0 += __shfl_xor_sync(0xffffffffu, rs0, 1);
        rs0 += __shfl_xor_sync(0xffffffffu, rs0, 2);
        rs1 += __shfl_xor_sync(0xffffffffu, rs1, 1);
        rs1 += __shfl_xor_sync(0xffffffffu, rs1, 2);
        l0r = l0r * sc0 + rs0;
        l1r = l1r * sc1 + rs1;
        m0r = mn0; m1r = mn1;
#pragma unroll
        for (int j = 0; j < 8; j++) {
            o[j][0] *= sc0; o[j][1] *= sc0;
            o[j][2] *= sc1; o[j][3] *= sc1;
        }

#pragma unroll
        for (int ks = 0; ks < 4; ks++) {
            uint32_t pa_h[4], pa_l[4];
            split_pack(s[2*ks][0],   s[2*ks][1],   pa_h[0], pa_l[0]);
            split_pack(s[2*ks][2],   s[2*ks][3],   pa_h[1], pa_l[1]);
            split_pack(s[2*ks+1][0], s[2*ks+1][1], pa_h[2], pa_l[2]);
            split_pack(s[2*ks+1][2], s[2*ks+1][3], pa_h[3], pa_l[3]);
#pragma unroll
            for (int d0 = 0; d0 < 4; d0++) {
                uint32_t vad = st + 2 * AT_QBUF +
                               (16 * ks + vrow) * AT_PITCH + (d0 * 16 + vcol) * 2;
                uint32_t vh2[4], vl2[4];
                LDSM4T(vh2, vad);
                LDSM4T(vl2, vad + AT_QBUF);
                const int dj = d0 * 2;
                mma_bf16(o[dj],   pa_h, vh2[0], vh2[2]);
                mma_bf16(o[dj],   pa_h, vl2[0], vl2[2]);
                mma_bf16(o[dj],   pa_l, vh2[0], vh2[2]);
                mma_bf16(o[dj+1], pa_h, vh2[1], vh2[3]);
                mma_bf16(o[dj+1], pa_h, vl2[1], vl2[3]);
                mma_bf16(o[dj+1], pa_l, vh2[1], vh2[3]);
            }
        }
    }

    const float rl0 = 1.0f / l0r, rl1 = 1.0f / l1r;
    const int row0 = b * S_ + qb + q0 + g;
    const int row1 = row0 + 8;
#pragma unroll
    for (int j = 0; j < 8; j++) {
        const int col = h * 64 + j * 8 + tig * 2;
        uint32_t h0, l0, h1, l1;
        split_pack(o[j][0] * rl0, o[j][1] * rl0, h0, l0);
        split_pack(o[j][2] * rl1, o[j][3] * rl1, h1, l1);
        *reinterpret_cast<uint32_t*>(ctxh + (size_t)row0 * M_ + col) = h0;
        *reinterpret_cast<uint32_t*>(ctxl + (size_t)row0 * M_ + col) = l0;
        *reinterpret_cast<uint32_t*>(ctxh + (size_t)row1 * M_ + col) = h1;
        *reinterpret_cast<uint32_t*>(ctxl + (size_t)row1 * M_ + col) = l1;
    }
}

// ---------------- layernorm ------------------------------------------------
__global__ __launch_bounds__(256)
void layernorm_k(const float* __restrict__ x, const float* __restrict__ g,
                 const float* __restrict__ bb, float* __restrict__ out)
{
    __shared__ float red[8];
    const int row = blockIdx.x, tid = threadIdx.x;
    const float4 v = reinterpret_cast<const float4*>(x + (size_t)row*1024)[tid];

    float s = v.x + v.y + v.z + v.w;
#pragma unroll
    for (int off = 16; off; off >>= 1) s += __shfl_xor_sync(0xffffffffu, s, off);
    if ((tid & 31) == 0) red[tid >> 5] = s;
    __syncthreads();
    if (tid < 32) {
        float t = (tid < 8) ? red[tid] : 0.f;
#pragma unroll
        for (int off = 4; off; off >>= 1) t += __shfl_xor_sync(0xffffffffu, t, off);
        if (tid == 0) red[0] = t;
    }
    __syncthreads();
    const float mean = red[0] * (1.0f / 1024.0f);
    const float dx = v.x - mean, dy = v.y - mean, dz = v.z - mean, dw = v.w - mean;
    float ss = dx*dx + dy*dy + dz*dz + dw*dw;
    __syncthreads();
#pragma unroll
    for (int off = 16; off; off >>= 1) ss += __shfl_xor_sync(0xffffffffu, ss, off);
    if ((tid & 31) == 0) red[tid >> 5] = ss;
    __syncthreads();
    if (tid < 32) {
        float t = (tid < 8) ? red[tid] : 0.f;
#pragma unroll
        for (int off = 4; off; off >>= 1) t += __shfl_xor_sync(0xffffffffu, t, off);
        if (tid == 0) red[0] = t;
    }
    __syncthreads();
    const float inv = rsqrtf(red[0] * (1.0f / 1024.0f) + 1e-5f);
    const int c = tid * 4;
    float4 o;
    o.x = dx * inv * g[c    ] + bb[c    ];
    o.y = dy * inv * g[c + 1] + bb[c + 1];
    o.z = dz * inv * g[c + 2] + bb[c + 2];
    o.w = dw * inv * g[c + 3] + bb[c + 3];
    reinterpret_cast<float4*>(out + (size_t)row*1024)[tid] = o;
}

// ---------------- launch ---------------------------------------------------
extern "C" void kernel_launch(void* const* d_in, const int* in_sizes, int n_in,
                              void* d_out, int out_size)
{
    const float* x     = (const float*)d_in[0];
    const float* W_enc = (const float*)d_in[1];
    const float* b_enc = (const float*)d_in[2];
    const float* Wq    = (const float*)d_in[3];
    const float* bq    = (const float*)d_in[4];
    const float* Wk    = (const float*)d_in[5];
    const float* bk    = (const float*)d_in[6];
    const float* Wv    = (const float*)d_in[7];
    const float* bv    = (const float*)d_in[8];
    const float* Wo    = (const float*)d_in[9];
    const float* bo    = (const float*)d_in[10];
    const float* ocr   = (const float*)d_in[11];
    const float* W1    = (const float*)d_in[12];
    const float* b1    = (const float*)d_in[13];
    const float* W2    = (const float*)d_in[14];
    const float* b2    = (const float*)d_in[15];
    const float* ln_g  = (const float*)d_in[16];
    const float* ln_b  = (const float*)d_in[17];
    float* out = (float*)d_out;

    __nv_bfloat16 *xh, *xl, *memh, *meml, *qkvh, *qkvl, *ctxh, *ctxl, *atth, *attl, *h1h, *h1l;
    __nv_bfloat16 *wench, *wencl, *wqkvh, *wqkvl, *woh, *wol, *w1h, *w1l, *w2h, *w2l;
    float *h2, *bqkv;
    cudaGetSymbolAddress((void**)&xh, g_x_h);     cudaGetSymbolAddress((void**)&xl, g_x_l);
    cudaGetSymbolAddress((void**)&memh, g_mem_h); cudaGetSymbolAddress((void**)&meml, g_mem_l);
    cudaGetSymbolAddress((void**)&qkvh, g_qkv_h); cudaGetSymbolAddress((void**)&qkvl, g_qkv_l);
    cudaGetSymbolAddress((void**)&ctxh, g_ctx_h); cudaGetSymbolAddress((void**)&ctxl, g_ctx_l);
    cudaGetSymbolAddress((void**)&atth, g_att_h); cudaGetSymbolAddress((void**)&attl, g_att_l);
    cudaGetSymbolAddress((void**)&h1h, g_h1_h);   cudaGetSymbolAddress((void**)&h1l, g_h1_l);
    cudaGetSymbolAddress((void**)&h2, g_h2);      cudaGetSymbolAddress((void**)&bqkv, g_bqkv);
    cudaGetSymbolAddress((void**)&wench, g_wenc_h); cudaGetSymbolAddress((void**)&wencl, g_wenc_l);
    cudaGetSymbolAddress((void**)&wqkvh, g_wqkv_h); cudaGetSymbolAddress((void**)&wqkvl, g_wqkv_l);
    cudaGetSymbolAddress((void**)&woh, g_wo_h);   cudaGetSymbolAddress((void**)&wol, g_wo_l);
    cudaGetSymbolAddress((void**)&w1h, g_w1_h);   cudaGetSymbolAddress((void**)&w1l, g_w1_l);
    cudaGetSymbolAddress((void**)&w2h, g_w2_h);   cudaGetSymbolAddress((void**)&w2l, g_w2_l);

    cudaFuncSetAttribute(attn_t,   cudaFuncAttributeMaxDynamicSharedMemorySize, ATTN_SMEM);
    cudaFuncSetAttribute(hgemm<0>, cudaFuncAttributeMaxDynamicSharedMemorySize, GEMM_SMEM);
    cudaFuncSetAttribute(hgemm<1>, cudaFuncAttributeMaxDynamicSharedMemorySize, GEMM_SMEM);
    cudaFuncSetAttribute(hgemm<2>, cudaFuncAttributeMaxDynamicSharedMemorySize, GEMM_SMEM);
    cudaFuncSetAttribute(hgemm<3>, cudaFuncAttributeMaxDynamicSharedMemorySize, GEMM_SMEM);

    // 1) weight prep (transpose + split) + bias concat; x split
    prep_w<<<4096, dim3(32, 8)>>>(W_enc, Wq, Wk, Wv, Wo, W1, W2, bq, bk, bv);
    prep_x<<<8192, 256>>>(x);

    dim3 blk(256);
    // 2) mem = x @ W_enc + b_enc -> planes           K=1024
    hgemm<0><<<dim3(4, 64), blk, GEMM_SMEM>>>(xh, xl, D_, D_, xh, xl, D_,
                                              wench, wencl, D_, b_enc, memh, meml, M_, D_);
    // 3) qkv = mem @ [Wq|Wk|Wv] + b -> scattered planes  N=1536, K=512
    hgemm<1><<<dim3(12, 64), blk, GEMM_SMEM>>>(memh, meml, M_, M_, memh, meml, M_,
                                               wqkvh, wqkvl, M_, bqkv, qkvh, qkvl, 0, M_);
    // 4) attention -> ctx planes
    attn_t<<<dim3(S_/64, B_*H_), 128, ATTN_SMEM>>>(qkvh, qkvl, ocr, ctxh, ctxl);
    // 5) att = ctx @ Wo + bo -> planes
    hgemm<0><<<dim3(4, 64), blk, GEMM_SMEM>>>(ctxh, ctxl, M_, M_, ctxh, ctxl, M_,
                                              woh, wol, M_, bo, atth, attl, M_, M_);
    // 6) h1 = gelu(concat(x, att) @ W1 + b1) -> planes   K=1536 (split A at 1024)
    hgemm<2><<<dim3(8, 64), blk, GEMM_SMEM>>>(xh, xl, D_, D_, atth, attl, M_,
                                              w1h, w1l, D_+M_, b1, h1h, h1l, D_, D_+M_);
    // 7) h2 = h1 @ W2 + b2 (fp32 out)
    hgemm<3><<<dim3(8, 64), blk, GEMM_SMEM>>>(h1h, h1l, D_, D_, h1h, h1l, D_,
                                              w2h, w2l, D_, b2, h2, nullptr, D_, D_);
    // 8) layernorm
    layernorm_k<<<R_, blk>>>(h2, ln_g, ln_b, out);
}

// round 6
// speedup vs baseline: 6.2539x; 2.5739x over previous
#include <cuda_runtime.h>
#include <cuda_fp16.h>
#include <math.h>
#include <stdint.h>

#define B_  4
#define S_  2048
#define D_  1024
#define M_  512
#define H_  8
#define R_  (B_*S_)   // 8192 token rows

// ---------------- scratch (device globals: no allocation) ----------------
__device__ __half g_x  [R_*D_];
__device__ __half g_mem[R_*M_];
__device__ __half g_qkv[3*R_*M_];      // [3][B][H][S][64]
__device__ __half g_ctx[R_*M_];
__device__ __half g_att[R_*M_];
__device__ __half g_h1 [R_*D_];
__device__ float  g_h2 [R_*D_];
__device__ float  g_bqkv[3*M_];
// weights transposed [N][K], fp16
__device__ __half g_wenc[M_*D_];
__device__ __half g_wqkv[3*M_*M_];
__device__ __half g_wo  [M_*M_];
__device__ __half g_w1  [D_*(D_+M_)];
__device__ __half g_w2  [D_*D_];

// ---------------- helpers ----------------
__device__ __forceinline__ uint32_t smem_u32(const void* p) {
    uint32_t a;
    asm("{ .reg .u64 t; cvta.to.shared.u64 t, %1; cvt.u32.u64 %0, t; }" : "=r"(a) : "l"(p));
    return a;
}
__device__ __forceinline__ uint32_t pack_h2(float a, float b) {
    __half2 h = __floats2half2_rn(a, b);
    return *reinterpret_cast<uint32_t*>(&h);
}
__device__ __forceinline__ float gelu_exact(float v) {
    return 0.5f * v * (1.0f + erff(v * 0.70710678118654752440f));
}
__device__ __forceinline__ void cp16(uint32_t s, const void* g) {
    asm volatile("cp.async.cg.shared.global [%0], [%1], 16;" :: "r"(s), "l"(g) : "memory");
}
#define CP_COMMIT() asm volatile("cp.async.commit_group;" ::: "memory")
#define CP_WAIT0()  asm volatile("cp.async.wait_group 0;" ::: "memory")
#define CP_WAIT1()  asm volatile("cp.async.wait_group 1;" ::: "memory")

#define LDSM4(r, addr) \
    asm volatile("ldmatrix.sync.aligned.m8n8.x4.shared.b16 {%0,%1,%2,%3}, [%4];" \
        : "=r"((r)[0]), "=r"((r)[1]), "=r"((r)[2]), "=r"((r)[3]) : "r"(addr))
#define LDSM4T(r, addr) \
    asm volatile("ldmatrix.sync.aligned.m8n8.x4.trans.shared.b16 {%0,%1,%2,%3}, [%4];" \
        : "=r"((r)[0]), "=r"((r)[1]), "=r"((r)[2]), "=r"((r)[3]) : "r"(addr))

__device__ __forceinline__ void mma_f16(float* c, const uint32_t* a, uint32_t b0, uint32_t b1) {
    asm volatile("mma.sync.aligned.m16n8k16.row.col.f32.f16.f16.f32 "
        "{%0,%1,%2,%3}, {%4,%5,%6,%7}, {%8,%9}, {%0,%1,%2,%3};"
        : "+f"(c[0]), "+f"(c[1]), "+f"(c[2]), "+f"(c[3])
        : "r"(a[0]), "r"(a[1]), "r"(a[2]), "r"(a[3]), "r"(b0), "r"(b1));
}

// ---------------- prep: transpose + fp16-convert weights, concat bias -----
__global__ void prep_w(const float* __restrict__ wenc, const float* __restrict__ wq,
                       const float* __restrict__ wk,   const float* __restrict__ wv,
                       const float* __restrict__ wo,   const float* __restrict__ w1,
                       const float* __restrict__ w2,
                       const float* __restrict__ bq, const float* __restrict__ bk,
                       const float* __restrict__ bv)
{
    __shared__ float t[32][33];
    int tw = blockIdx.x;
    const float* src; __half* dh; int K, N;
    if      (tw < 512)  {            src = wenc; dh = g_wenc; K = 1024; N = 512; }
    else if (tw < 768)  { tw -= 512;  src = wq; dh = g_wqkv;              K = 512; N = 512; }
    else if (tw < 1024) { tw -= 768;  src = wk; dh = g_wqkv + 512*512;    K = 512; N = 512; }
    else if (tw < 1280) { tw -= 1024; src = wv; dh = g_wqkv + 2*512*512;  K = 512; N = 512; }
    else if (tw < 1536) { tw -= 1280; src = wo; dh = g_wo; K = 512; N = 512; }
    else if (tw < 3072) { tw -= 1536; src = w1; dh = g_w1; K = 1536; N = 1024; }
    else                { tw -= 3072; src = w2; dh = g_w2; K = 1024; N = 1024; }

    const int tilesx = N / 32;
    const int kb = (tw / tilesx) * 32, nb = (tw % tilesx) * 32;
    const int x = threadIdx.x, y = threadIdx.y;  // 32 x 8
#pragma unroll
    for (int j = 0; j < 32; j += 8)
        t[y + j][x] = src[(size_t)(kb + y + j) * N + nb + x];
    __syncthreads();
#pragma unroll
    for (int j = 0; j < 32; j += 8)
        dh[(size_t)(nb + y + j) * K + kb + x] = __float2half_rn(t[x][y + j]);
    if (blockIdx.x == 0) {
        int tid = y * 32 + x;
        for (int i = tid; i < 1536; i += 256)
            g_bqkv[i] = (i < 512) ? bq[i] : (i < 1024) ? bk[i - 512] : bv[i - 1024];
    }
}

// ---------------- prep: convert x -----------------------------------------
__global__ void prep_x(const float* __restrict__ x)
{
    const size_t i = ((size_t)blockIdx.x * 256 + threadIdx.x) * 4;
    float4 v = *reinterpret_cast<const float4*>(x + i);
    *reinterpret_cast<uint2*>(g_x + i) = make_uint2(pack_h2(v.x, v.y), pack_h2(v.z, v.w));
}

// ---------------- fp16 GEMM, BK=32, 3-stage ring, 2 CTAs/SM ---------------
// C = A @ Bt^T. Tile 128x128, 256 thr, warp tile 32x64.
// EPI 0: half out + bias; EPI 1: QKV scatter half; EPI 2: gelu -> half;
// EPI 3: fp32 out + bias
#define ABUF  8192                  // 128 rows x 64 B (32 fp16), swizzled
#define STAGE_BYTES (2*ABUF)        // A, B = 16384
#define GEMM_SMEM (3*STAGE_BYTES)   // 49152

template<int EPI>
__global__ __launch_bounds__(256, 2)
void hgemm(const __half* __restrict__ A1, int lda1, int KA,
           const __half* __restrict__ A2, int lda2,
           const __half* __restrict__ Bt, int ldb,
           const float* __restrict__ bias,
           void* __restrict__ o1, int ldc, int K)
{
    extern __shared__ char sm_[];
    const uint32_t sb = smem_u32(sm_);
    const int tid = threadIdx.x, wid = tid >> 5, lane = tid & 31;
    const int bm = blockIdx.y * 128, bn = blockIdx.x * 128;
    const int m0 = (wid & 3) * 32, n0 = (wid >> 2) * 64;

    float acc[2][8][4];
#pragma unroll
    for (int i = 0; i < 2; i++)
#pragma unroll
        for (int j = 0; j < 8; j++)
#pragma unroll
            for (int t = 0; t < 4; t++) acc[i][j][t] = 0.f;

    // cp.async slots: 512 16B-slots per plane; 2 per thread
    auto LOADCP = [&](int c, int buf) {
        const int k0 = c * 32;
        const __half* ap; int ld, ko;
        if (k0 < KA) { ap = A1; ld = lda1; ko = k0; }
        else         { ap = A2; ld = lda2; ko = k0 - KA; }
        const uint32_t st = sb + buf * STAGE_BYTES;
#pragma unroll
        for (int p = 0; p < 2; p++) {
            int s = tid + p * 256;
            int r = s >> 2, k16 = s & 3;
            uint32_t so = r * 64 + ((k16 ^ ((r >> 1) & 3)) << 4);
            cp16(st + so,        ap + (size_t)(bm + r) * ld + ko + k16 * 8);
            cp16(st + ABUF + so, Bt + (size_t)(bn + r) * ldb + k0 + k16 * 8);
        }
    };

    // ldmatrix lane offsets at ks=0; ks=1 -> XOR 0x20
    const int i4 = lane >> 3, l7 = lane & 7;
    const int khalf = i4 >> 1;
    uint32_t aoffs[2], boffs[4];
#pragma unroll
    for (int mi = 0; mi < 2; mi++) {
        int row = m0 + mi * 16 + ((i4 & 1) << 3) + l7;
        aoffs[mi] = row * 64 + ((khalf ^ ((row >> 1) & 3)) << 4);
    }
#pragma unroll
    for (int nj = 0; nj < 4; nj++) {
        int row = n0 + nj * 16 + ((i4 & 1) << 3) + l7;
        boffs[nj] = row * 64 + ((khalf ^ ((row >> 1) & 3)) << 4);
    }

    auto MMA = [&](int buf) {
        const uint32_t bA = sb + buf * STAGE_BYTES;
        const uint32_t bB = bA + ABUF;
#pragma unroll
        for (int ks = 0; ks < 2; ks++) {
            const uint32_t kx = ks << 5;
            uint32_t av[2][4];
            LDSM4(av[0], bA + (aoffs[0] ^ kx));
            LDSM4(av[1], bA + (aoffs[1] ^ kx));
#pragma unroll
            for (int nj = 0; nj < 4; nj++) {
                uint32_t bv[4];
                LDSM4(bv, bB + (boffs[nj] ^ kx));
                mma_f16(acc[0][nj*2],   av[0], bv[0], bv[2]);
                mma_f16(acc[0][nj*2+1], av[0], bv[1], bv[3]);
                mma_f16(acc[1][nj*2],   av[1], bv[0], bv[2]);
                mma_f16(acc[1][nj*2+1], av[1], bv[1], bv[3]);
            }
        }
    };

    const int NC = K >> 5;
    LOADCP(0, 0); CP_COMMIT();
    LOADCP(1, 1); CP_COMMIT();
    for (int c = 0; c < NC; c++) {
        CP_WAIT1();
        __syncthreads();
        if (c + 2 < NC) { LOADCP(c + 2, (c + 2) % 3); CP_COMMIT(); }
        MMA(c % 3);
    }

    // ---- epilogue ----
    const int g = lane >> 2, tig = lane & 3;
#pragma unroll
    for (int mi = 0; mi < 2; mi++) {
#pragma unroll
        for (int nf = 0; nf < 8; nf++) {
            const int col = bn + n0 + nf * 8 + tig * 2;
            const int r0  = bm + m0 + mi * 16 + g;
            const int r1  = r0 + 8;
            float b0v = bias ? bias[col] : 0.f;
            float b1v = bias ? bias[col + 1] : 0.f;
            float v00 = acc[mi][nf][0] + b0v, v01 = acc[mi][nf][1] + b1v;
            float v10 = acc[mi][nf][2] + b0v, v11 = acc[mi][nf][3] + b1v;
            if (EPI == 2) {
                v00 = gelu_exact(v00); v01 = gelu_exact(v01);
                v10 = gelu_exact(v10); v11 = gelu_exact(v11);
            }
            if (EPI == 3) {
                float* C = (float*)o1;
                *reinterpret_cast<float2*>(C + (size_t)r0 * ldc + col) = make_float2(v00, v01);
                *reinterpret_cast<float2*>(C + (size_t)r1 * ldc + col) = make_float2(v10, v11);
            } else {
                __half* Ch = (__half*)o1;
                if (EPI == 1) {
                    const int tns = col >> 9, rem = col & 511;
                    const int hh = rem >> 6, dd = rem & 63;
                    size_t oa = ((((size_t)(tns*4 + (r0 >> 11)) * 8 + hh) * 2048 + (r0 & 2047)) * 64 + dd);
                    size_t ob = ((((size_t)(tns*4 + (r1 >> 11)) * 8 + hh) * 2048 + (r1 & 2047)) * 64 + dd);
                    *reinterpret_cast<uint32_t*>(Ch + oa) = pack_h2(v00, v01);
                    *reinterpret_cast<uint32_t*>(Ch + ob) = pack_h2(v10, v11);
                } else {
                    *reinterpret_cast<uint32_t*>(Ch + (size_t)r0 * ldc + col) = pack_h2(v00, v01);
                    *reinterpret_cast<uint32_t*>(Ch + (size_t)r1 * ldc + col) = pack_h2(v10, v11);
                }
            }
        }
    }
}

// ---------------- fp16 tensor-core flash attention -------------------------
#define AT_PITCH 144
#define AT_QBUF  (64*AT_PITCH)               // 9216
#define AT_STAGE (2*AT_QBUF)                 // K + V = 18432
#define ATTN_SMEM (AT_QBUF + 2*AT_STAGE)     // 46080

__global__ __launch_bounds__(128, 3)
void attn_t(const __half* __restrict__ qkv, const float* __restrict__ ocr,
            __half* __restrict__ ctx)
{
    extern __shared__ char sm_[];
    const uint32_t sb = smem_u32(sm_);
    const int tid = threadIdx.x, wid = tid >> 5, lane = tid & 31;
    const int bh = blockIdx.y;
    const int b = bh >> 3, h = bh & 7;
    const int qb = blockIdx.x * 64;
    const float hb = ocr[h];

    const size_t base = (size_t)bh * S_ * 64;
    const size_t ksec = (size_t)R_ * M_;
    const size_t vsec = 2 * ksec;

#pragma unroll
    for (int i = 0; i < 4; i++) {
        int idx = tid + i * 128;
        int r = idx >> 3, cc = (idx & 7) * 16;
        cp16(sb + r * AT_PITCH + cc, (const char*)(qkv + base + (size_t)(qb + r) * 64) + cc);
    }

    auto LOADKV = [&](int c, int buf) {
        const int kb = c * 64;
        const uint32_t st = sb + AT_QBUF + buf * AT_STAGE;
#pragma unroll
        for (int i = 0; i < 4; i++) {
            int idx = tid + i * 128;
            int r = idx >> 3, cc = (idx & 7) * 16;
            size_t go = base + (size_t)(kb + r) * 64;
            cp16(st + r * AT_PITCH + cc,            (const char*)(qkv + ksec + go) + cc);
            cp16(st + AT_QBUF + r * AT_PITCH + cc,  (const char*)(qkv + vsec + go) + cc);
        }
    };

    LOADKV(0, 0);
    CP_COMMIT();

    const int q0 = wid * 16;
    const int i4 = lane >> 3, l7 = lane & 7;
    const int g = lane >> 2, tig = lane & 3;
    const uint32_t aoff = (uint32_t)((q0 + ((i4 & 1) << 3) + l7) * AT_PITCH + ((i4 >> 1) << 4));
    const uint32_t koff = (uint32_t)((((i4 & 1) << 3) + l7) * AT_PITCH + ((i4 >> 1) << 4));
    const int vrow = ((lane >> 4) & 1) * 8 + (lane & 7);
    const int vcol = ((lane >> 3) & 1) * 8;

    float m0r = -1e30f, m1r = -1e30f, l0r = 0.f, l1r = 0.f;
    float o[8][4];
#pragma unroll
    for (int j = 0; j < 8; j++)
#pragma unroll
        for (int t = 0; t < 4; t++) o[j][t] = 0.f;

    for (int c = 0; c < 32; c++) {
        CP_WAIT0();
        __syncthreads();
        if (c + 1 < 32) { LOADKV(c + 1, (c + 1) & 1); CP_COMMIT(); }

        const uint32_t st = sb + AT_QBUF + (c & 1) * AT_STAGE;

        // ---- scores = Q @ K^T ----
        float s[8][4];
#pragma unroll
        for (int j = 0; j < 8; j++)
#pragma unroll
            for (int t = 0; t < 4; t++) s[j][t] = 0.f;
#pragma unroll
        for (int ks = 0; ks < 4; ks++) {
            uint32_t qv[4];
            LDSM4(qv, sb + aoff + ks * 32);
#pragma unroll
            for (int nj = 0; nj < 4; nj++) {
                uint32_t kv[4];
                LDSM4(kv, st + koff + nj * 16 * AT_PITCH + ks * 32);
                mma_f16(s[nj*2],   qv, kv[0], kv[2]);
                mma_f16(s[nj*2+1], qv, kv[1], kv[3]);
            }
        }

        // ---- online softmax ----
        float mx0 = -1e30f, mx1 = -1e30f;
#pragma unroll
        for (int j = 0; j < 8; j++) {
            s[j][0] = s[j][0] * 0.125f + hb;
            s[j][1] = s[j][1] * 0.125f + hb;
            s[j][2] = s[j][2] * 0.125f + hb;
            s[j][3] = s[j][3] * 0.125f + hb;
            mx0 = fmaxf(mx0, fmaxf(s[j][0], s[j][1]));
            mx1 = fmaxf(mx1, fmaxf(s[j][2], s[j][3]));
        }
        mx0 = fmaxf(mx0, __shfl_xor_sync(0xffffffffu, mx0, 1));
        mx0 = fmaxf(mx0, __shfl_xor_sync(0xffffffffu, mx0, 2));
        mx1 = fmaxf(mx1, __shfl_xor_sync(0xffffffffu, mx1, 1));
        mx1 = fmaxf(mx1, __shfl_xor_sync(0xffffffffu, mx1, 2));
        const float mn0 = fmaxf(m0r, mx0), mn1 = fmaxf(m1r, mx1);
        const float sc0 = __expf(m0r - mn0), sc1 = __expf(m1r - mn1);
        float rs0 = 0.f, rs1 = 0.f;
#pragma unroll
        for (int j = 0; j < 8; j++) {
            s[j][0] = __expf(s[j][0] - mn0);
            s[j][1] = __expf(s[j][1] - mn0);
            s[j][2] = __expf(s[j][2] - mn1);
            s[j][3] = __expf(s[j][3] - mn1);
            rs0 += s[j][0] + s[j][1];
            rs1 += s[j][2] + s[j][3];
        }
        rs0 += __shfl_xor_sync(0xffffffffu, rs0, 1);
        rs0 += __shfl_xor_sync(0xffffffffu, rs0, 2);
        rs1 += __shfl_xor_sync(0xffffffffu, rs1, 1);
        rs1 += __shfl_xor_sync(0xffffffffu, rs1, 2);
        l0r = l0r * sc0 + rs0;
        l1r = l1r * sc1 + rs1;
        m0r = mn0; m1r = mn1;
#pragma unroll
        for (int j = 0; j < 8; j++) {
            o[j][0] *= sc0; o[j][1] *= sc0;
            o[j][2] *= sc1; o[j][3] *= sc1;
        }

        // ---- ctx += P @ V ----
#pragma unroll
        for (int ks = 0; ks < 4; ks++) {
            uint32_t pa[4];
            pa[0] = pack_h2(s[2*ks][0],   s[2*ks][1]);
            pa[1] = pack_h2(s[2*ks][2],   s[2*ks][3]);
            pa[2] = pack_h2(s[2*ks+1][0], s[2*ks+1][1]);
            pa[3] = pack_h2(s[2*ks+1][2], s[2*ks+1][3]);
#pragma unroll
            for (int d0 = 0; d0 < 4; d0++) {
                uint32_t vv[4];
                LDSM4T(vv, st + AT_QBUF + (16 * ks + vrow) * AT_PITCH + (d0 * 16 + vcol) * 2);
                const int dj = d0 * 2;
                mma_f16(o[dj],   pa, vv[0], vv[2]);
                mma_f16(o[dj+1], pa, vv[1], vv[3]);
            }
        }
    }

    // ---- write ctx half [b, s, h*64+d] ----
    const float rl0 = 1.0f / l0r, rl1 = 1.0f / l1r;
    const int row0 = b * S_ + qb + q0 + g;
    const int row1 = row0 + 8;
#pragma unroll
    for (int j = 0; j < 8; j++) {
        const int col = h * 64 + j * 8 + tig * 2;
        *reinterpret_cast<uint32_t*>(ctx + (size_t)row0 * M_ + col) = pack_h2(o[j][0]*rl0, o[j][1]*rl0);
        *reinterpret_cast<uint32_t*>(ctx + (size_t)row1 * M_ + col) = pack_h2(o[j][2]*rl1, o[j][3]*rl1);
    }
}

// ---------------- layernorm ------------------------------------------------
__global__ __launch_bounds__(256)
void layernorm_k(const float* __restrict__ x, const float* __restrict__ g,
                 const float* __restrict__ bb, float* __restrict__ out)
{
    __shared__ float red[8];
    const int row = blockIdx.x, tid = threadIdx.x;
    const float4 v = reinterpret_cast<const float4*>(x + (size_t)row*1024)[tid];

    float s = v.x + v.y + v.z + v.w;
#pragma unroll
    for (int off = 16; off; off >>= 1) s += __shfl_xor_sync(0xffffffffu, s, off);
    if ((tid & 31) == 0) red[tid >> 5] = s;
    __syncthreads();
    if (tid < 32) {
        float t = (tid < 8) ? red[tid] : 0.f;
#pragma unroll
        for (int off = 4; off; off >>= 1) t += __shfl_xor_sync(0xffffffffu, t, off);
        if (tid == 0) red[0] = t;
    }
    __syncthreads();
    const float mean = red[0] * (1.0f / 1024.0f);
    const float dx = v.x - mean, dy = v.y - mean, dz = v.z - mean, dw = v.w - mean;
    float ss = dx*dx + dy*dy + dz*dz + dw*dw;
    __syncthreads();
#pragma unroll
    for (int off = 16; off; off >>= 1) ss += __shfl_xor_sync(0xffffffffu, ss, off);
    if ((tid & 31) == 0) red[tid >> 5] = ss;
    __syncthreads();
    if (tid < 32) {
        float t = (tid < 8) ? red[tid] : 0.f;
#pragma unroll
        for (int off = 4; off; off >>= 1) t += __shfl_xor_sync(0xffffffffu, t, off);
        if (tid == 0) red[0] = t;
    }
    __syncthreads();
    const float inv = rsqrtf(red[0] * (1.0f / 1024.0f) + 1e-5f);
    const int c = tid * 4;
    float4 o;
    o.x = dx * inv * g[c    ] + bb[c    ];
    o.y = dy * inv * g[c + 1] + bb[c + 1];
    o.z = dz * inv * g[c + 2] + bb[c + 2];
    o.w = dw * inv * g[c + 3] + bb[c + 3];
    reinterpret_cast<float4*>(out + (size_t)row*1024)[tid] = o;
}

// ---------------- launch ---------------------------------------------------
extern "C" void kernel_launch(void* const* d_in, const int* in_sizes, int n_in,
                              void* d_out, int out_size)
{
    const float* x     = (const float*)d_in[0];
    const float* W_enc = (const float*)d_in[1];
    const float* b_enc = (const float*)d_in[2];
    const float* Wq    = (const float*)d_in[3];
    const float* bq    = (const float*)d_in[4];
    const float* Wk    = (const float*)d_in[5];
    const float* bk    = (const float*)d_in[6];
    const float* Wv    = (const float*)d_in[7];
    const float* bv    = (const float*)d_in[8];
    const float* Wo    = (const float*)d_in[9];
    const float* bo    = (const float*)d_in[10];
    const float* ocr   = (const float*)d_in[11];
    const float* W1    = (const float*)d_in[12];
    const float* b1    = (const float*)d_in[13];
    const float* W2    = (const float*)d_in[14];
    const float* b2    = (const float*)d_in[15];
    const float* ln_g  = (const float*)d_in[16];
    const float* ln_b  = (const float*)d_in[17];
    float* out = (float*)d_out;

    __half *xh, *mem, *qkv, *ctx, *att, *h1;
    __half *wenc, *wqkv, *wo, *w1, *w2;
    float *h2, *bqkv;
    cudaGetSymbolAddress((void**)&xh,  g_x);
    cudaGetSymbolAddress((void**)&mem, g_mem);
    cudaGetSymbolAddress((void**)&qkv, g_qkv);
    cudaGetSymbolAddress((void**)&ctx, g_ctx);
    cudaGetSymbolAddress((void**)&att, g_att);
    cudaGetSymbolAddress((void**)&h1,  g_h1);
    cudaGetSymbolAddress((void**)&h2,  g_h2);
    cudaGetSymbolAddress((void**)&bqkv, g_bqkv);
    cudaGetSymbolAddress((void**)&wenc, g_wenc);
    cudaGetSymbolAddress((void**)&wqkv, g_wqkv);
    cudaGetSymbolAddress((void**)&wo, g_wo);
    cudaGetSymbolAddress((void**)&w1, g_w1);
    cudaGetSymbolAddress((void**)&w2, g_w2);

    cudaFuncSetAttribute(attn_t,   cudaFuncAttributeMaxDynamicSharedMemorySize, ATTN_SMEM);
    cudaFuncSetAttribute(hgemm<0>, cudaFuncAttributeMaxDynamicSharedMemorySize, GEMM_SMEM);
    cudaFuncSetAttribute(hgemm<1>, cudaFuncAttributeMaxDynamicSharedMemorySize, GEMM_SMEM);
    cudaFuncSetAttribute(hgemm<2>, cudaFuncAttributeMaxDynamicSharedMemorySize, GEMM_SMEM);
    cudaFuncSetAttribute(hgemm<3>, cudaFuncAttributeMaxDynamicSharedMemorySize, GEMM_SMEM);

    // 1) prep: weights (transpose + fp16) + bias concat; x fp16
    prep_w<<<4096, dim3(32, 8)>>>(W_enc, Wq, Wk, Wv, Wo, W1, W2, bq, bk, bv);
    prep_x<<<8192, 256>>>(x);

    dim3 blk(256);
    // 2) mem = x @ W_enc + b_enc              K=1024
    hgemm<0><<<dim3(4, 64), blk, GEMM_SMEM>>>(xh, D_, D_, xh, D_, wenc, D_, b_enc, mem, M_, D_);
    // 3) qkv = mem @ [Wq|Wk|Wv] + b -> scattered [3][B,H,S,64]  N=1536, K=512
    hgemm<1><<<dim3(12, 64), blk, GEMM_SMEM>>>(mem, M_, M_, mem, M_, wqkv, M_, bqkv, qkv, 0, M_);
    // 4) attention -> ctx [b,s,(h,d)]
    attn_t<<<dim3(S_/64, B_*H_), 128, ATTN_SMEM>>>(qkv, ocr, ctx);
    // 5) att = ctx @ Wo + bo
    hgemm<0><<<dim3(4, 64), blk, GEMM_SMEM>>>(ctx, M_, M_, ctx, M_, wo, M_, bo, att, M_, M_);
    // 6) h1 = gelu(concat(x, att) @ W1 + b1)   K=1536 (split A at 1024)
    hgemm<2><<<dim3(8, 64), blk, GEMM_SMEM>>>(xh, D_, D_, att, M_, w1, D_+M_, b1, h1, D_, D_+M_);
    // 7) h2 = h1 @ W2 + b2 (fp32 out)
    hgemm<3><<<dim3(8, 64), blk, GEMM_SMEM>>>(h1, D_, D_, h1, D_, w2, D_, b2, h2, D_, D_);
    // 8) layernorm
    layernorm_k<<<R_, blk>>>(h2, ln_g, ln_b, out);
}

// round 7
// speedup vs baseline: 6.4116x; 1.0252x over previous
#include <cuda_runtime.h>
#include <cuda_fp16.h>
#include <math.h>
#include <stdint.h>

#define B_  4
#define S_  2048
#define D_  1024
#define M_  512
#define H_  8
#define R_  (B_*S_)   // 8192 token rows

// ---------------- scratch (device globals: no allocation) ----------------
__device__ __half g_x  [R_*D_];
__device__ __half g_mem[R_*M_];
__device__ __half g_qkv[3*R_*M_];      // [3][B][H][S][64]
__device__ __half g_ctx[R_*M_];
__device__ __half g_att[R_*M_];
__device__ __half g_h1 [R_*D_];
__device__ float  g_h2 [R_*D_];
__device__ float  g_bqkv[3*M_];
// weights transposed [N][K], fp16
__device__ __half g_wenc[M_*D_];
__device__ __half g_wqkv[3*M_*M_];
__device__ __half g_wo  [M_*M_];
__device__ __half g_w1  [D_*(D_+M_)];
__device__ __half g_w2  [D_*D_];

// ---------------- helpers ----------------
__device__ __forceinline__ uint32_t smem_u32(const void* p) {
    uint32_t a;
    asm("{ .reg .u64 t; cvta.to.shared.u64 t, %1; cvt.u32.u64 %0, t; }" : "=r"(a) : "l"(p));
    return a;
}
__device__ __forceinline__ uint32_t pack_h2(float a, float b) {
    __half2 h = __floats2half2_rn(a, b);
    return *reinterpret_cast<uint32_t*>(&h);
}
__device__ __forceinline__ float gelu_exact(float v) {
    return 0.5f * v * (1.0f + erff(v * 0.70710678118654752440f));
}
__device__ __forceinline__ void cp16(uint32_t s, const void* g) {
    asm volatile("cp.async.cg.shared.global [%0], [%1], 16;" :: "r"(s), "l"(g) : "memory");
}
#define CP_COMMIT() asm volatile("cp.async.commit_group;" ::: "memory")
#define CP_WAIT0()  asm volatile("cp.async.wait_group 0;" ::: "memory")
#define CP_WAIT2()  asm volatile("cp.async.wait_group 2;" ::: "memory")

#define LDSM4(r, addr) \
    asm volatile("ldmatrix.sync.aligned.m8n8.x4.shared.b16 {%0,%1,%2,%3}, [%4];" \
        : "=r"((r)[0]), "=r"((r)[1]), "=r"((r)[2]), "=r"((r)[3]) : "r"(addr))
#define LDSM4T(r, addr) \
    asm volatile("ldmatrix.sync.aligned.m8n8.x4.trans.shared.b16 {%0,%1,%2,%3}, [%4];" \
        : "=r"((r)[0]), "=r"((r)[1]), "=r"((r)[2]), "=r"((r)[3]) : "r"(addr))

__device__ __forceinline__ void mma_f16(float* c, const uint32_t* a, uint32_t b0, uint32_t b1) {
    asm volatile("mma.sync.aligned.m16n8k16.row.col.f32.f16.f16.f32 "
        "{%0,%1,%2,%3}, {%4,%5,%6,%7}, {%8,%9}, {%0,%1,%2,%3};"
        : "+f"(c[0]), "+f"(c[1]), "+f"(c[2]), "+f"(c[3])
        : "r"(a[0]), "r"(a[1]), "r"(a[2]), "r"(a[3]), "r"(b0), "r"(b1));
}

// ---------------- prep: transpose + fp16-convert weights, concat bias -----
__global__ void prep_w(const float* __restrict__ wenc, const float* __restrict__ wq,
                       const float* __restrict__ wk,   const float* __restrict__ wv,
                       const float* __restrict__ wo,   const float* __restrict__ w1,
                       const float* __restrict__ w2,
                       const float* __restrict__ bq, const float* __restrict__ bk,
                       const float* __restrict__ bv)
{
    __shared__ float t[32][33];
    int tw = blockIdx.x;
    const float* src; __half* dh; int K, N;
    if      (tw < 512)  {            src = wenc; dh = g_wenc; K = 1024; N = 512; }
    else if (tw < 768)  { tw -= 512;  src = wq; dh = g_wqkv;              K = 512; N = 512; }
    else if (tw < 1024) { tw -= 768;  src = wk; dh = g_wqkv + 512*512;    K = 512; N = 512; }
    else if (tw < 1280) { tw -= 1024; src = wv; dh = g_wqkv + 2*512*512;  K = 512; N = 512; }
    else if (tw < 1536) { tw -= 1280; src = wo; dh = g_wo; K = 512; N = 512; }
    else if (tw < 3072) { tw -= 1536; src = w1; dh = g_w1; K = 1536; N = 1024; }
    else                { tw -= 3072; src = w2; dh = g_w2; K = 1024; N = 1024; }

    const int tilesx = N / 32;
    const int kb = (tw / tilesx) * 32, nb = (tw % tilesx) * 32;
    const int x = threadIdx.x, y = threadIdx.y;  // 32 x 8
#pragma unroll
    for (int j = 0; j < 32; j += 8)
        t[y + j][x] = src[(size_t)(kb + y + j) * N + nb + x];
    __syncthreads();
#pragma unroll
    for (int j = 0; j < 32; j += 8)
        dh[(size_t)(nb + y + j) * K + kb + x] = __float2half_rn(t[x][y + j]);
    if (blockIdx.x == 0) {
        int tid = y * 32 + x;
        for (int i = tid; i < 1536; i += 256)
            g_bqkv[i] = (i < 512) ? bq[i] : (i < 1024) ? bk[i - 512] : bv[i - 1024];
    }
}

// ---------------- prep: convert x -----------------------------------------
__global__ void prep_x(const float* __restrict__ x)
{
    const size_t i = ((size_t)blockIdx.x * 256 + threadIdx.x) * 4;
    float4 v = *reinterpret_cast<const float4*>(x + i);
    *reinterpret_cast<uint2*>(g_x + i) = make_uint2(pack_h2(v.x, v.y), pack_h2(v.z, v.w));
}

// ---------------- fp16 GEMM, BK=32, 4-stage ring, 2 CTAs/SM ---------------
// C = A @ Bt^T. Tile 128x128, 256 thr, warp tile 32x64.
// Software-pipelined fragment loads: all A frags + B(ks0) batched up front,
// B(ks1) in flight during MMA(ks0).
#define ABUF  8192                  // 128 rows x 64 B (32 fp16), swizzled
#define STAGE_BYTES (2*ABUF)        // A, B = 16384
#define NSTAGE 4
#define GEMM_SMEM (NSTAGE*STAGE_BYTES)   // 65536

template<int EPI>
__global__ __launch_bounds__(256, 2)
void hgemm(const __half* __restrict__ A1, int lda1, int KA,
           const __half* __restrict__ A2, int lda2,
           const __half* __restrict__ Bt, int ldb,
           const float* __restrict__ bias,
           void* __restrict__ o1, int ldc, int K)
{
    extern __shared__ char sm_[];
    const uint32_t sb = smem_u32(sm_);
    const int tid = threadIdx.x, wid = tid >> 5, lane = tid & 31;
    const int bm = blockIdx.y * 128, bn = blockIdx.x * 128;
    const int m0 = (wid & 3) * 32, n0 = (wid >> 2) * 64;

    float acc[2][8][4];
#pragma unroll
    for (int i = 0; i < 2; i++)
#pragma unroll
        for (int j = 0; j < 8; j++)
#pragma unroll
            for (int t = 0; t < 4; t++) acc[i][j][t] = 0.f;

    // cp.async: 2 16B slots per thread per plane; precomputed offsets
    const int cpr = tid >> 2, cpk = tid & 3;
    const uint32_t cps0 = (uint32_t)(cpr * 64 + ((cpk ^ ((cpr >> 1) & 3)) << 4));
    const int cpr1 = (tid + 256) >> 2;  // = cpr + 64
    const uint32_t cps1 = (uint32_t)(cpr1 * 64 + ((cpk ^ ((cpr1 >> 1) & 3)) << 4));
    const int cpe = cpk * 8;

    auto LOADCP = [&](int c, int buf) {
        const int k0 = c * 32;
        const __half* ap; int ld, ko;
        if (k0 < KA) { ap = A1; ld = lda1; ko = k0; }
        else         { ap = A2; ld = lda2; ko = k0 - KA; }
        const uint32_t st = sb + buf * STAGE_BYTES;
        cp16(st + cps0,        ap + (size_t)(bm + cpr)  * ld + ko + cpe);
        cp16(st + cps1,        ap + (size_t)(bm + cpr1) * ld + ko + cpe);
        cp16(st + ABUF + cps0, Bt + (size_t)(bn + cpr)  * ldb + k0 + cpe);
        cp16(st + ABUF + cps1, Bt + (size_t)(bn + cpr1) * ldb + k0 + cpe);
    };

    // ldmatrix lane offsets at ks=0; ks=1 -> XOR 0x20
    const int i4 = lane >> 3, l7 = lane & 7;
    const int khalf = i4 >> 1;
    uint32_t aoffs[2], boffs[4];
#pragma unroll
    for (int mi = 0; mi < 2; mi++) {
        int row = m0 + mi * 16 + ((i4 & 1) << 3) + l7;
        aoffs[mi] = row * 64 + ((khalf ^ ((row >> 1) & 3)) << 4);
    }
#pragma unroll
    for (int nj = 0; nj < 4; nj++) {
        int row = n0 + nj * 16 + ((i4 & 1) << 3) + l7;
        boffs[nj] = row * 64 + ((khalf ^ ((row >> 1) & 3)) << 4);
    }

    const int NC = K >> 5;
    LOADCP(0, 0); CP_COMMIT();
    if (NC > 1) { LOADCP(1, 1); } CP_COMMIT();
    if (NC > 2) { LOADCP(2, 2); } CP_COMMIT();

    for (int c = 0; c < NC; c++) {
        CP_WAIT2();
        __syncthreads();
        const uint32_t bA = sb + (c & 3) * STAGE_BYTES;
        const uint32_t bB = bA + ABUF;

        // batch LDSM: A both ks, B ks0
        uint32_t a0[2][4], a1[2][4], b0[4][4], b1[4][4];
        LDSM4(a0[0], bA + aoffs[0]);
        LDSM4(a0[1], bA + aoffs[1]);
        LDSM4(a1[0], bA + (aoffs[0] ^ 32));
        LDSM4(a1[1], bA + (aoffs[1] ^ 32));
#pragma unroll
        for (int nj = 0; nj < 4; nj++) LDSM4(b0[nj], bB + boffs[nj]);

        // issue next chunk's gmem loads while frags arrive
        if (c + 3 < NC) { LOADCP(c + 3, (c + 3) & 3); }
        CP_COMMIT();

        // B ks1 in flight during MMA ks0
#pragma unroll
        for (int nj = 0; nj < 4; nj++) LDSM4(b1[nj], bB + (boffs[nj] ^ 32));

#pragma unroll
        for (int nj = 0; nj < 4; nj++) {
            mma_f16(acc[0][nj*2],   a0[0], b0[nj][0], b0[nj][2]);
            mma_f16(acc[0][nj*2+1], a0[0], b0[nj][1], b0[nj][3]);
            mma_f16(acc[1][nj*2],   a0[1], b0[nj][0], b0[nj][2]);
            mma_f16(acc[1][nj*2+1], a0[1], b0[nj][1], b0[nj][3]);
        }
#pragma unroll
        for (int nj = 0; nj < 4; nj++) {
            mma_f16(acc[0][nj*2],   a1[0], b1[nj][0], b1[nj][2]);
            mma_f16(acc[0][nj*2+1], a1[0], b1[nj][1], b1[nj][3]);
            mma_f16(acc[1][nj*2],   a1[1], b1[nj][0], b1[nj][2]);
            mma_f16(acc[1][nj*2+1], a1[1], b1[nj][1], b1[nj][3]);
        }
    }

    // ---- epilogue ----
    const int g = lane >> 2, tig = lane & 3;
#pragma unroll
    for (int mi = 0; mi < 2; mi++) {
#pragma unroll
        for (int nf = 0; nf < 8; nf++) {
            const int col = bn + n0 + nf * 8 + tig * 2;
            const int r0  = bm + m0 + mi * 16 + g;
            const int r1  = r0 + 8;
            float b0v = bias ? bias[col] : 0.f;
            float b1v = bias ? bias[col + 1] : 0.f;
            float v00 = acc[mi][nf][0] + b0v, v01 = acc[mi][nf][1] + b1v;
            float v10 = acc[mi][nf][2] + b0v, v11 = acc[mi][nf][3] + b1v;
            if (EPI == 2) {
                v00 = gelu_exact(v00); v01 = gelu_exact(v01);
                v10 = gelu_exact(v10); v11 = gelu_exact(v11);
            }
            if (EPI == 3) {
                float* C = (float*)o1;
                *reinterpret_cast<float2*>(C + (size_t)r0 * ldc + col) = make_float2(v00, v01);
                *reinterpret_cast<float2*>(C + (size_t)r1 * ldc + col) = make_float2(v10, v11);
            } else {
                __half* Ch = (__half*)o1;
                if (EPI == 1) {
                    const int tns = col >> 9, rem = col & 511;
                    const int hh = rem >> 6, dd = rem & 63;
                    size_t oa = ((((size_t)(tns*4 + (r0 >> 11)) * 8 + hh) * 2048 + (r0 & 2047)) * 64 + dd);
                    size_t ob = ((((size_t)(tns*4 + (r1 >> 11)) * 8 + hh) * 2048 + (r1 & 2047)) * 64 + dd);
                    *reinterpret_cast<uint32_t*>(Ch + oa) = pack_h2(v00, v01);
                    *reinterpret_cast<uint32_t*>(Ch + ob) = pack_h2(v10, v11);
                } else {
                    *reinterpret_cast<uint32_t*>(Ch + (size_t)r0 * ldc + col) = pack_h2(v00, v01);
                    *reinterpret_cast<uint32_t*>(Ch + (size_t)r1 * ldc + col) = pack_h2(v10, v11);
                }
            }
        }
    }
}

// ---------------- fp16 tensor-core flash attention -------------------------
#define AT_PITCH 144
#define AT_QBUF  (64*AT_PITCH)               // 9216
#define AT_STAGE (2*AT_QBUF)                 // K + V = 18432
#define ATTN_SMEM (AT_QBUF + 2*AT_STAGE)     // 46080

__global__ __launch_bounds__(128, 3)
void attn_t(const __half* __restrict__ qkv, const float* __restrict__ ocr,
            __half* __restrict__ ctx)
{
    extern __shared__ char sm_[];
    const uint32_t sb = smem_u32(sm_);
    const int tid = threadIdx.x, wid = tid >> 5, lane = tid & 31;
    const int bh = blockIdx.y;
    const int b = bh >> 3, h = bh & 7;
    const int qb = blockIdx.x * 64;
    const float hb = ocr[h];

    const size_t base = (size_t)bh * S_ * 64;
    const size_t ksec = (size_t)R_ * M_;
    const size_t vsec = 2 * ksec;

#pragma unroll
    for (int i = 0; i < 4; i++) {
        int idx = tid + i * 128;
        int r = idx >> 3, cc = (idx & 7) * 16;
        cp16(sb + r * AT_PITCH + cc, (const char*)(qkv + base + (size_t)(qb + r) * 64) + cc);
    }

    auto LOADKV = [&](int c, int buf) {
        const int kb = c * 64;
        const uint32_t st = sb + AT_QBUF + buf * AT_STAGE;
#pragma unroll
        for (int i = 0; i < 4; i++) {
            int idx = tid + i * 128;
            int r = idx >> 3, cc = (idx & 7) * 16;
            size_t go = base + (size_t)(kb + r) * 64;
            cp16(st + r * AT_PITCH + cc,            (const char*)(qkv + ksec + go) + cc);
            cp16(st + AT_QBUF + r * AT_PITCH + cc,  (const char*)(qkv + vsec + go) + cc);
        }
    };

    LOADKV(0, 0);
    CP_COMMIT();

    const int q0 = wid * 16;
    const int i4 = lane >> 3, l7 = lane & 7;
    const int g = lane >> 2, tig = lane & 3;
    const uint32_t aoff = (uint32_t)((q0 + ((i4 & 1) << 3) + l7) * AT_PITCH + ((i4 >> 1) << 4));
    const uint32_t koff = (uint32_t)((((i4 & 1) << 3) + l7) * AT_PITCH + ((i4 >> 1) << 4));
    const int vrow = ((lane >> 4) & 1) * 8 + (lane & 7);
    const int vcol = ((lane >> 3) & 1) * 8;

    // Q frags are loop-invariant: load once after Q arrives (first wait covers it)
    float m0r = -1e30f, m1r = -1e30f, l0r = 0.f, l1r = 0.f;
    float o[8][4];
#pragma unroll
    for (int j = 0; j < 8; j++)
#pragma unroll
        for (int t = 0; t < 4; t++) o[j][t] = 0.f;

    uint32_t qv[4][4];
    bool qloaded = false;

    for (int c = 0; c < 32; c++) {
        CP_WAIT0();
        __syncthreads();
        if (c + 1 < 32) { LOADKV(c + 1, (c + 1) & 1); CP_COMMIT(); }

        if (!qloaded) {
#pragma unroll
            for (int ks = 0; ks < 4; ks++) LDSM4(qv[ks], sb + aoff + ks * 32);
            qloaded = true;
        }

        const uint32_t st = sb + AT_QBUF + (c & 1) * AT_STAGE;

        // ---- scores = Q @ K^T ----
        float s[8][4];
#pragma unroll
        for (int j = 0; j < 8; j++)
#pragma unroll
            for (int t = 0; t < 4; t++) s[j][t] = 0.f;
#pragma unroll
        for (int ks = 0; ks < 4; ks++) {
#pragma unroll
            for (int nj = 0; nj < 4; nj++) {
                uint32_t kv[4];
                LDSM4(kv, st + koff + nj * 16 * AT_PITCH + ks * 32);
                mma_f16(s[nj*2],   qv[ks], kv[0], kv[2]);
                mma_f16(s[nj*2+1], qv[ks], kv[1], kv[3]);
            }
        }

        // ---- online softmax ----
        float mx0 = -1e30f, mx1 = -1e30f;
#pragma unroll
        for (int j = 0; j < 8; j++) {
            s[j][0] = s[j][0] * 0.125f + hb;
            s[j][1] = s[j][1] * 0.125f + hb;
            s[j][2] = s[j][2] * 0.125f + hb;
            s[j][3] = s[j][3] * 0.125f + hb;
            mx0 = fmaxf(mx0, fmaxf(s[j][0], s[j][1]));
            mx1 = fmaxf(mx1, fmaxf(s[j][2], s[j][3]));
        }
        mx0 = fmaxf(mx0, __shfl_xor_sync(0xffffffffu, mx0, 1));
        mx0 = fmaxf(mx0, __shfl_xor_sync(0xffffffffu, mx0, 2));
        mx1 = fmaxf(mx1, __shfl_xor_sync(0xffffffffu, mx1, 1));
        mx1 = fmaxf(mx1, __shfl_xor_sync(0xffffffffu, mx1, 2));
        const float mn0 = fmaxf(m0r, mx0), mn1 = fmaxf(m1r, mx1);
        const float sc0 = __expf(m0r - mn0), sc1 = __expf(m1r - mn1);
        float rs0 = 0.f, rs1 = 0.f;
#pragma unroll
        for (int j = 0; j < 8; j++) {
            s[j][0] = __expf(s[j][0] - mn0);
            s[j][1] = __expf(s[j][1] - mn0);
            s[j][2] = __expf(s[j][2] - mn1);
            s[j][3] = __expf(s[j][3] - mn1);
            rs0 += s[j][0] + s[j][1];
            rs1 += s[j][2] + s[j][3];
        }
        rs0 += __shfl_xor_sync(0xffffffffu, rs0, 1);
        rs0 += __shfl_xor_sync(0xffffffffu, rs0, 2);
        rs1 += __shfl_xor_sync(0xffffffffu, rs1, 1);
        rs1 += __shfl_xor_sync(0xffffffffu, rs1, 2);
        l0r = l0r * sc0 + rs0;
        l1r = l1r * sc1 + rs1;
        m0r = mn0; m1r = mn1;
#pragma unroll
        for (int j = 0; j < 8; j++) {
            o[j][0] *= sc0; o[j][1] *= sc0;
            o[j][2] *= sc1; o[j][3] *= sc1;
        }

        // ---- ctx += P @ V ----
#pragma unroll
        for (int ks = 0; ks < 4; ks++) {
            uint32_t pa[4];
            pa[0] = pack_h2(s[2*ks][0],   s[2*ks][1]);
            pa[1] = pack_h2(s[2*ks][2],   s[2*ks][3]);
            pa[2] = pack_h2(s[2*ks+1][0], s[2*ks+1][1]);
            pa[3] = pack_h2(s[2*ks+1][2], s[2*ks+1][3]);
#pragma unroll
            for (int d0 = 0; d0 < 4; d0++) {
                uint32_t vv[4];
                LDSM4T(vv, st + AT_QBUF + (16 * ks + vrow) * AT_PITCH + (d0 * 16 + vcol) * 2);
                const int dj = d0 * 2;
                mma_f16(o[dj],   pa, vv[0], vv[2]);
                mma_f16(o[dj+1], pa, vv[1], vv[3]);
            }
        }
    }

    // ---- write ctx half [b, s, h*64+d] ----
    const float rl0 = 1.0f / l0r, rl1 = 1.0f / l1r;
    const int row0 = b * S_ + qb + q0 + g;
    const int row1 = row0 + 8;
#pragma unroll
    for (int j = 0; j < 8; j++) {
        const int col = h * 64 + j * 8 + tig * 2;
        *reinterpret_cast<uint32_t*>(ctx + (size_t)row0 * M_ + col) = pack_h2(o[j][0]*rl0, o[j][1]*rl0);
        *reinterpret_cast<uint32_t*>(ctx + (size_t)row1 * M_ + col) = pack_h2(o[j][2]*rl1, o[j][3]*rl1);
    }
}

// ---------------- layernorm ------------------------------------------------
__global__ __launch_bounds__(256)
void layernorm_k(const float* __restrict__ x, const float* __restrict__ g,
                 const float* __restrict__ bb, float* __restrict__ out)
{
    __shared__ float red[8];
    const int row = blockIdx.x, tid = threadIdx.x;
    const float4 v = reinterpret_cast<const float4*>(x + (size_t)row*1024)[tid];

    float s = v.x + v.y + v.z + v.w;
#pragma unroll
    for (int off = 16; off; off >>= 1) s += __shfl_xor_sync(0xffffffffu, s, off);
    if ((tid & 31) == 0) red[tid >> 5] = s;
    __syncthreads();
    if (tid < 32) {
        float t = (tid < 8) ? red[tid] : 0.f;
#pragma unroll
        for (int off = 4; off; off >>= 1) t += __shfl_xor_sync(0xffffffffu, t, off);
        if (tid == 0) red[0] = t;
    }
    __syncthreads();
    const float mean = red[0] * (1.0f / 1024.0f);
    const float dx = v.x - mean, dy = v.y - mean, dz = v.z - mean, dw = v.w - mean;
    float ss = dx*dx + dy*dy + dz*dz + dw*dw;
    __syncthreads();
#pragma unroll
    for (int off = 16; off; off >>= 1) ss += __shfl_xor_sync(0xffffffffu, ss, off);
    if ((tid & 31) == 0) red[tid >> 5] = ss;
    __syncthreads();
    if (tid < 32) {
        float t = (tid < 8) ? red[tid] : 0.f;
#pragma unroll
        for (int off = 4; off; off >>= 1) t += __shfl_xor_sync(0xffffffffu, t, off);
        if (tid == 0) red[0] = t;
    }
    __syncthreads();
    const float inv = rsqrtf(red[0] * (1.0f / 1024.0f) + 1e-5f);
    const int c = tid * 4;
    float4 o;
    o.x = dx * inv * g[c    ] + bb[c    ];
    o.y = dy * inv * g[c + 1] + bb[c + 1];
    o.z = dz * inv * g[c + 2] + bb[c + 2];
    o.w = dw * inv * g[c + 3] + bb[c + 3];
    reinterpret_cast<float4*>(out + (size_t)row*1024)[tid] = o;
}

// ---------------- launch ---------------------------------------------------
extern "C" void kernel_launch(void* const* d_in, const int* in_sizes, int n_in,
                              void* d_out, int out_size)
{
    const float* x     = (const float*)d_in[0];
    const float* W_enc = (const float*)d_in[1];
    const float* b_enc = (const float*)d_in[2];
    const float* Wq    = (const float*)d_in[3];
    const float* bq    = (const float*)d_in[4];
    const float* Wk    = (const float*)d_in[5];
    const float* bk    = (const float*)d_in[6];
    const float* Wv    = (const float*)d_in[7];
    const float* bv    = (const float*)d_in[8];
    const float* Wo    = (const float*)d_in[9];
    const float* bo    = (const float*)d_in[10];
    const float* ocr   = (const float*)d_in[11];
    const float* W1    = (const float*)d_in[12];
    const float* b1    = (const float*)d_in[13];
    const float* W2    = (const float*)d_in[14];
    const float* b2    = (const float*)d_in[15];
    const float* ln_g  = (const float*)d_in[16];
    const float* ln_b  = (const float*)d_in[17];
    float* out = (float*)d_out;

    __half *xh, *mem, *qkv, *ctx, *att, *h1;
    __half *wenc, *wqkv, *wo, *w1, *w2;
    float *h2, *bqkv;
    cudaGetSymbolAddress((void**)&xh,  g_x);
    cudaGetSymbolAddress((void**)&mem, g_mem);
    cudaGetSymbolAddress((void**)&qkv, g_qkv);
    cudaGetSymbolAddress((void**)&ctx, g_ctx);
    cudaGetSymbolAddress((void**)&att, g_att);
    cudaGetSymbolAddress((void**)&h1,  g_h1);
    cudaGetSymbolAddress((void**)&h2,  g_h2);
    cudaGetSymbolAddress((void**)&bqkv, g_bqkv);
    cudaGetSymbolAddress((void**)&wenc, g_wenc);
    cudaGetSymbolAddress((void**)&wqkv, g_wqkv);
    cudaGetSymbolAddress((void**)&wo, g_wo);
    cudaGetSymbolAddress((void**)&w1, g_w1);
    cudaGetSymbolAddress((void**)&w2, g_w2);

    cudaFuncSetAttribute(attn_t,   cudaFuncAttributeMaxDynamicSharedMemorySize, ATTN_SMEM);
    cudaFuncSetAttribute(hgemm<0>, cudaFuncAttributeMaxDynamicSharedMemorySize, GEMM_SMEM);
    cudaFuncSetAttribute(hgemm<1>, cudaFuncAttributeMaxDynamicSharedMemorySize, GEMM_SMEM);
    cudaFuncSetAttribute(hgemm<2>, cudaFuncAttributeMaxDynamicSharedMemorySize, GEMM_SMEM);
    cudaFuncSetAttribute(hgemm<3>, cudaFuncAttributeMaxDynamicSharedMemorySize, GEMM_SMEM);

    // 1) prep: weights (transpose + fp16) + bias concat; x fp16
    prep_w<<<4096, dim3(32, 8)>>>(W_enc, Wq, Wk, Wv, Wo, W1, W2, bq, bk, bv);
    prep_x<<<8192, 256>>>(x);

    dim3 blk(256);
    // 2) mem = x @ W_enc + b_enc              K=1024
    hgemm<0><<<dim3(4, 64), blk, GEMM_SMEM>>>(xh, D_, D_, xh, D_, wenc, D_, b_enc, mem, M_, D_);
    // 3) qkv = mem @ [Wq|Wk|Wv] + b -> scattered [3][B,H,S,64]  N=1536, K=512
    hgemm<1><<<dim3(12, 64), blk, GEMM_SMEM>>>(mem, M_, M_, mem, M_, wqkv, M_, bqkv, qkv, 0, M_);
    // 4) attention -> ctx [b,s,(h,d)]
    attn_t<<<dim3(S_/64, B_*H_), 128, ATTN_SMEM>>>(qkv, ocr, ctx);
    // 5) att = ctx @ Wo + bo
    hgemm<0><<<dim3(4, 64), blk, GEMM_SMEM>>>(ctx, M_, M_, ctx, M_, wo, M_, bo, att, M_, M_);
    // 6) h1 = gelu(concat(x, att) @ W1 + b1)   K=1536 (split A at 1024)
    hgemm<2><<<dim3(8, 64), blk, GEMM_SMEM>>>(xh, D_, D_, att, M_, w1, D_+M_, b1, h1, D_, D_+M_);
    // 7) h2 = h1 @ W2 + b2 (fp32 out)
    hgemm<3><<<dim3(8, 64), blk, GEMM_SMEM>>>(h1, D_, D_, h1, D_, w2, D_, b2, h2, D_, D_);
    // 8) layernorm
    layernorm_k<<<R_, blk>>>(h2, ln_g, ln_b, out);
}

// round 8
// speedup vs baseline: 6.4972x; 1.0133x over previous
#include <cuda_runtime.h>
#include <cuda_fp16.h>
#include <math.h>
#include <stdint.h>

#define B_  4
#define S_  2048
#define D_  1024
#define M_  512
#define H_  8
#define R_  (B_*S_)   // 8192 token rows

// ---------------- scratch (device globals: no allocation) ----------------
__device__ __half g_x  [R_*D_];
__device__ __half g_mem[R_*M_];
__device__ __half g_qkv[3*R_*M_];      // [3][B][H][S][64]
__device__ __half g_ctx[R_*M_];
__device__ __half g_att[R_*M_];
__device__ __half g_h1 [R_*D_];
__device__ float  g_h2 [R_*D_];        // fp32 staging (w1 x-part, then w2 out)
__device__ float  g_bqkv[3*M_];
// weights transposed [N][K], fp16
__device__ __half g_wenc[M_*D_];
__device__ __half g_wqkv[3*M_*M_];
__device__ __half g_wo  [M_*M_];
__device__ __half g_w1  [D_*(D_+M_)];
__device__ __half g_w2  [D_*D_];

// ---------------- helpers ----------------
__device__ __forceinline__ uint32_t smem_u32(const void* p) {
    uint32_t a;
    asm("{ .reg .u64 t; cvta.to.shared.u64 t, %1; cvt.u32.u64 %0, t; }" : "=r"(a) : "l"(p));
    return a;
}
__device__ __forceinline__ uint32_t pack_h2(float a, float b) {
    __half2 h = __floats2half2_rn(a, b);
    return *reinterpret_cast<uint32_t*>(&h);
}
__device__ __forceinline__ float gelu_exact(float v) {
    return 0.5f * v * (1.0f + erff(v * 0.70710678118654752440f));
}
__device__ __forceinline__ void cp16(uint32_t s, const void* g) {
    asm volatile("cp.async.cg.shared.global [%0], [%1], 16;" :: "r"(s), "l"(g) : "memory");
}
#define CP_COMMIT() asm volatile("cp.async.commit_group;" ::: "memory")
#define CP_WAIT0()  asm volatile("cp.async.wait_group 0;" ::: "memory")
#define CP_WAIT2()  asm volatile("cp.async.wait_group 2;" ::: "memory")

#define LDSM4(r, addr) \
    asm volatile("ldmatrix.sync.aligned.m8n8.x4.shared.b16 {%0,%1,%2,%3}, [%4];" \
        : "=r"((r)[0]), "=r"((r)[1]), "=r"((r)[2]), "=r"((r)[3]) : "r"(addr))
#define LDSM4T(r, addr) \
    asm volatile("ldmatrix.sync.aligned.m8n8.x4.trans.shared.b16 {%0,%1,%2,%3}, [%4];" \
        : "=r"((r)[0]), "=r"((r)[1]), "=r"((r)[2]), "=r"((r)[3]) : "r"(addr))

__device__ __forceinline__ void mma_f16(float* c, const uint32_t* a, uint32_t b0, uint32_t b1) {
    asm volatile("mma.sync.aligned.m16n8k16.row.col.f32.f16.f16.f32 "
        "{%0,%1,%2,%3}, {%4,%5,%6,%7}, {%8,%9}, {%0,%1,%2,%3};"
        : "+f"(c[0]), "+f"(c[1]), "+f"(c[2]), "+f"(c[3])
        : "r"(a[0]), "r"(a[1]), "r"(a[2]), "r"(a[3]), "r"(b0), "r"(b1));
}

// ---------------- prep: transpose + fp16-convert weights, concat bias -----
__global__ void prep_w(const float* __restrict__ wenc, const float* __restrict__ wq,
                       const float* __restrict__ wk,   const float* __restrict__ wv,
                       const float* __restrict__ wo,   const float* __restrict__ w1,
                       const float* __restrict__ w2,
                       const float* __restrict__ bq, const float* __restrict__ bk,
                       const float* __restrict__ bv)
{
    __shared__ float t[32][33];
    int tw = blockIdx.x;
    const float* src; __half* dh; int K, N;
    if      (tw < 512)  {            src = wenc; dh = g_wenc; K = 1024; N = 512; }
    else if (tw < 768)  { tw -= 512;  src = wq; dh = g_wqkv;              K = 512; N = 512; }
    else if (tw < 1024) { tw -= 768;  src = wk; dh = g_wqkv + 512*512;    K = 512; N = 512; }
    else if (tw < 1280) { tw -= 1024; src = wv; dh = g_wqkv + 2*512*512;  K = 512; N = 512; }
    else if (tw < 1536) { tw -= 1280; src = wo; dh = g_wo; K = 512; N = 512; }
    else if (tw < 3072) { tw -= 1536; src = w1; dh = g_w1; K = 1536; N = 1024; }
    else                { tw -= 3072; src = w2; dh = g_w2; K = 1024; N = 1024; }

    const int tilesx = N / 32;
    const int kb = (tw / tilesx) * 32, nb = (tw % tilesx) * 32;
    const int x = threadIdx.x, y = threadIdx.y;  // 32 x 8
#pragma unroll
    for (int j = 0; j < 32; j += 8)
        t[y + j][x] = src[(size_t)(kb + y + j) * N + nb + x];
    __syncthreads();
#pragma unroll
    for (int j = 0; j < 32; j += 8)
        dh[(size_t)(nb + y + j) * K + kb + x] = __float2half_rn(t[x][y + j]);
    if (blockIdx.x == 0) {
        int tid = y * 32 + x;
        for (int i = tid; i < 1536; i += 256)
            g_bqkv[i] = (i < 512) ? bq[i] : (i < 1024) ? bk[i - 512] : bv[i - 1024];
    }
}

// ---------------- prep: convert x -----------------------------------------
__global__ void prep_x(const float* __restrict__ x)
{
    const size_t i = ((size_t)blockIdx.x * 256 + threadIdx.x) * 4;
    float4 v = *reinterpret_cast<const float4*>(x + i);
    *reinterpret_cast<uint2*>(g_x + i) = make_uint2(pack_h2(v.x, v.y), pack_h2(v.z, v.w));
}

// ---------------- fp16 GEMM body, BK=32, 4-stage ring ----------------------
// C = A @ Bt^T. Tile 128x128, 256 thr, warp tile 32x64.
// EPI 0: half out + bias; EPI 1: QKV scatter half; EPI 3: fp32 out + bias;
// EPI 4: half out = gelu(i2_read_fp32 + acc)
#define ABUF  8192                  // 128 rows x 64 B (32 fp16), swizzled
#define STAGE_BYTES (2*ABUF)        // A, B = 16384
#define GEMM_SMEM (4*STAGE_BYTES)   // 65536

template<int EPI>
__device__ __forceinline__ void hgemm_body(
    char* sm_, int bm, int bn,
    const __half* __restrict__ A1, int lda1, int KA,
    const __half* __restrict__ A2, int lda2,
    const __half* __restrict__ Bt, int ldb,
    const float* __restrict__ bias,
    void* __restrict__ o1, const float* __restrict__ i2, int ldc, int K)
{
    const uint32_t sb = smem_u32(sm_);
    const int tid = threadIdx.x, wid = tid >> 5, lane = tid & 31;
    const int m0 = (wid & 3) * 32, n0 = (wid >> 2) * 64;

    float acc[2][8][4];
#pragma unroll
    for (int i = 0; i < 2; i++)
#pragma unroll
        for (int j = 0; j < 8; j++)
#pragma unroll
            for (int t = 0; t < 4; t++) acc[i][j][t] = 0.f;

    const int cpr = tid >> 2, cpk = tid & 3;
    const uint32_t cps0 = (uint32_t)(cpr * 64 + ((cpk ^ ((cpr >> 1) & 3)) << 4));
    const int cpr1 = cpr + 64;
    const uint32_t cps1 = (uint32_t)(cpr1 * 64 + ((cpk ^ ((cpr1 >> 1) & 3)) << 4));
    const int cpe = cpk * 8;

    auto LOADCP = [&](int c, int buf) {
        const int k0 = c * 32;
        const __half* ap; int ld, ko;
        if (k0 < KA) { ap = A1; ld = lda1; ko = k0; }
        else         { ap = A2; ld = lda2; ko = k0 - KA; }
        const uint32_t st = sb + buf * STAGE_BYTES;
        cp16(st + cps0,        ap + (size_t)(bm + cpr)  * ld + ko + cpe);
        cp16(st + cps1,        ap + (size_t)(bm + cpr1) * ld + ko + cpe);
        cp16(st + ABUF + cps0, Bt + (size_t)(bn + cpr)  * ldb + k0 + cpe);
        cp16(st + ABUF + cps1, Bt + (size_t)(bn + cpr1) * ldb + k0 + cpe);
    };

    const int i4 = lane >> 3, l7 = lane & 7;
    const int khalf = i4 >> 1;
    uint32_t aoffs[2], boffs[4];
#pragma unroll
    for (int mi = 0; mi < 2; mi++) {
        int row = m0 + mi * 16 + ((i4 & 1) << 3) + l7;
        aoffs[mi] = row * 64 + ((khalf ^ ((row >> 1) & 3)) << 4);
    }
#pragma unroll
    for (int nj = 0; nj < 4; nj++) {
        int row = n0 + nj * 16 + ((i4 & 1) << 3) + l7;
        boffs[nj] = row * 64 + ((khalf ^ ((row >> 1) & 3)) << 4);
    }

    const int NC = K >> 5;
    LOADCP(0, 0); CP_COMMIT();
    if (NC > 1) { LOADCP(1, 1); } CP_COMMIT();
    if (NC > 2) { LOADCP(2, 2); } CP_COMMIT();

    for (int c = 0; c < NC; c++) {
        CP_WAIT2();
        __syncthreads();
        const uint32_t bA = sb + (c & 3) * STAGE_BYTES;
        const uint32_t bB = bA + ABUF;

        uint32_t a0[2][4], a1[2][4];
        LDSM4(a0[0], bA + aoffs[0]);
        LDSM4(a0[1], bA + aoffs[1]);
        LDSM4(a1[0], bA + (aoffs[0] ^ 32));
        LDSM4(a1[1], bA + (aoffs[1] ^ 32));

        if (c + 3 < NC) { LOADCP(c + 3, (c + 3) & 3); }
        CP_COMMIT();

        uint32_t bfr[2][4];
        LDSM4(bfr[0], bB + boffs[0]);
#pragma unroll
        for (int t = 0; t < 8; t++) {
            const int nj = t & 3, ks = t >> 2;
            if (t < 7) {
                const int t2 = t + 1;
                LDSM4(bfr[t2 & 1], bB + (boffs[t2 & 3] ^ ((t2 >> 2) << 5)));
            }
            const uint32_t (*av)[4] = ks ? a1 : a0;
            const uint32_t* bv = bfr[t & 1];
            mma_f16(acc[0][nj*2],   av[0], bv[0], bv[2]);
            mma_f16(acc[0][nj*2+1], av[0], bv[1], bv[3]);
            mma_f16(acc[1][nj*2],   av[1], bv[0], bv[2]);
            mma_f16(acc[1][nj*2+1], av[1], bv[1], bv[3]);
        }
    }

    // ---- epilogue ----
    const int g = lane >> 2, tig = lane & 3;
#pragma unroll
    for (int mi = 0; mi < 2; mi++) {
#pragma unroll
        for (int nf = 0; nf < 8; nf++) {
            const int col = bn + n0 + nf * 8 + tig * 2;
            const int r0  = bm + m0 + mi * 16 + g;
            const int r1  = r0 + 8;
            float b0v = 0.f, b1v = 0.f;
            if (EPI != 4 && bias) { b0v = bias[col]; b1v = bias[col + 1]; }
            float v00 = acc[mi][nf][0] + b0v, v01 = acc[mi][nf][1] + b1v;
            float v10 = acc[mi][nf][2] + b0v, v11 = acc[mi][nf][3] + b1v;
            if (EPI == 3) {
                float* C = (float*)o1;
                *reinterpret_cast<float2*>(C + (size_t)r0 * ldc + col) = make_float2(v00, v01);
                *reinterpret_cast<float2*>(C + (size_t)r1 * ldc + col) = make_float2(v10, v11);
            } else if (EPI == 4) {
                float2 p0 = *reinterpret_cast<const float2*>(i2 + (size_t)r0 * ldc + col);
                float2 p1 = *reinterpret_cast<const float2*>(i2 + (size_t)r1 * ldc + col);
                v00 = gelu_exact(p0.x + v00); v01 = gelu_exact(p0.y + v01);
                v10 = gelu_exact(p1.x + v10); v11 = gelu_exact(p1.y + v11);
                __half* Ch = (__half*)o1;
                *reinterpret_cast<uint32_t*>(Ch + (size_t)r0 * ldc + col) = pack_h2(v00, v01);
                *reinterpret_cast<uint32_t*>(Ch + (size_t)r1 * ldc + col) = pack_h2(v10, v11);
            } else {
                __half* Ch = (__half*)o1;
                if (EPI == 1) {
                    const int tns = col >> 9, rem = col & 511;
                    const int hh = rem >> 6, dd = rem & 63;
                    size_t oa = ((((size_t)(tns*4 + (r0 >> 11)) * 8 + hh) * 2048 + (r0 & 2047)) * 64 + dd);
                    size_t ob = ((((size_t)(tns*4 + (r1 >> 11)) * 8 + hh) * 2048 + (r1 & 2047)) * 64 + dd);
                    *reinterpret_cast<uint32_t*>(Ch + oa) = pack_h2(v00, v01);
                    *reinterpret_cast<uint32_t*>(Ch + ob) = pack_h2(v10, v11);
                } else {
                    *reinterpret_cast<uint32_t*>(Ch + (size_t)r0 * ldc + col) = pack_h2(v00, v01);
                    *reinterpret_cast<uint32_t*>(Ch + (size_t)r1 * ldc + col) = pack_h2(v10, v11);
                }
            }
        }
    }
}

template<int EPI>
__global__ __launch_bounds__(256, 2)
void hgemm(const __half* __restrict__ A1, int lda1, int KA,
           const __half* __restrict__ A2, int lda2,
           const __half* __restrict__ Bt, int ldb,
           const float* __restrict__ bias,
           void* __restrict__ o1, const float* __restrict__ i2, int ldc, int K)
{
    extern __shared__ char sm_[];
    hgemm_body<EPI>(sm_, blockIdx.y * 128, blockIdx.x * 128,
                    A1, lda1, KA, A2, lda2, Bt, ldb, bias, o1, i2, ldc, K);
}

// ---------------- fp16 flash attention body: 128-query tile, 8 warps ------
#define AT_PITCH 144
#define AT_QBUF  9216                        // V offset within a stage (64*144)
#define AT_Q2BUF (128*AT_PITCH)              // 18432 (Q tile)
#define AT_STAGE (2*AT_QBUF)                 // K + V = 18432

__device__ __forceinline__ void attn_body(
    char* sm_, int abid,
    const __half* __restrict__ qkv, const float* __restrict__ ocr,
    __half* __restrict__ ctx)
{
    const uint32_t sb = smem_u32(sm_);
    const int tid = threadIdx.x, wid = tid >> 5, lane = tid & 31;
    const int bh = abid >> 4;       // 16 q-tiles of 128 per (b,h)
    const int qt = abid & 15;
    const int b = bh >> 3, h = bh & 7;
    const int qb = qt * 128;
    const float hb = ocr[h];

    const size_t base = (size_t)bh * S_ * 64;
    const size_t ksec = (size_t)R_ * M_;
    const size_t vsec = 2 * ksec;

    // Q tile: 128 rows x 128B = 1024 16B-slots, 4 per thread
#pragma unroll
    for (int i = 0; i < 4; i++) {
        int idx = tid + i * 256;
        int r = idx >> 3, cc = (idx & 7) * 16;
        cp16(sb + r * AT_PITCH + cc, (const char*)(qkv + base + (size_t)(qb + r) * 64) + cc);
    }

    auto LOADKV = [&](int c, int buf) {
        const int kb = c * 64;
        const uint32_t st = sb + AT_Q2BUF + buf * AT_STAGE;
#pragma unroll
        for (int i = 0; i < 2; i++) {
            int idx = tid + i * 256;
            int r = idx >> 3, cc = (idx & 7) * 16;
            size_t go = base + (size_t)(kb + r) * 64;
            cp16(st + r * AT_PITCH + cc,            (const char*)(qkv + ksec + go) + cc);
            cp16(st + AT_QBUF + r * AT_PITCH + cc,  (const char*)(qkv + vsec + go) + cc);
        }
    };

    LOADKV(0, 0);
    CP_COMMIT();

    const int q0 = wid * 16;
    const int i4 = lane >> 3, l7 = lane & 7;
    const int g = lane >> 2, tig = lane & 3;
    const uint32_t aoff = (uint32_t)((q0 + ((i4 & 1) << 3) + l7) * AT_PITCH + ((i4 >> 1) << 4));
    const uint32_t koff = (uint32_t)((((i4 & 1) << 3) + l7) * AT_PITCH + ((i4 >> 1) << 4));
    const int vrow = ((lane >> 4) & 1) * 8 + (lane & 7);
    const int vcol = ((lane >> 3) & 1) * 8;

    float m0r = -1e30f, m1r = -1e30f, l0r = 0.f, l1r = 0.f;
    float o[8][4];
#pragma unroll
    for (int j = 0; j < 8; j++)
#pragma unroll
        for (int t = 0; t < 4; t++) o[j][t] = 0.f;

    uint32_t qv[4][4];
    bool qloaded = false;

    for (int c = 0; c < 32; c++) {
        CP_WAIT0();
        __syncthreads();
        if (c + 1 < 32) { LOADKV(c + 1, (c + 1) & 1); CP_COMMIT(); }

        if (!qloaded) {
#pragma unroll
            for (int ks = 0; ks < 4; ks++) LDSM4(qv[ks], sb + aoff + ks * 32);
            qloaded = true;
        }

        const uint32_t st = sb + AT_Q2BUF + (c & 1) * AT_STAGE;

        // ---- scores = Q @ K^T ----
        float s[8][4];
#pragma unroll
        for (int j = 0; j < 8; j++)
#pragma unroll
            for (int t = 0; t < 4; t++) s[j][t] = 0.f;
#pragma unroll
        for (int ks = 0; ks < 4; ks++) {
#pragma unroll
            for (int nj = 0; nj < 4; nj++) {
                uint32_t kv[4];
                LDSM4(kv, st + koff + nj * 16 * AT_PITCH + ks * 32);
                mma_f16(s[nj*2],   qv[ks], kv[0], kv[2]);
                mma_f16(s[nj*2+1], qv[ks], kv[1], kv[3]);
            }
        }

        // ---- online softmax ----
        float mx0 = -1e30f, mx1 = -1e30f;
#pragma unroll
        for (int j = 0; j < 8; j++) {
            s[j][0] = s[j][0] * 0.125f + hb;
            s[j][1] = s[j][1] * 0.125f + hb;
            s[j][2] = s[j][2] * 0.125f + hb;
            s[j][3] = s[j][3] * 0.125f + hb;
            mx0 = fmaxf(mx0, fmaxf(s[j][0], s[j][1]));
            mx1 = fmaxf(mx1, fmaxf(s[j][2], s[j][3]));
        }
        mx0 = fmaxf(mx0, __shfl_xor_sync(0xffffffffu, mx0, 1));
        mx0 = fmaxf(mx0, __shfl_xor_sync(0xffffffffu, mx0, 2));
        mx1 = fmaxf(mx1, __shfl_xor_sync(0xffffffffu, mx1, 1));
        mx1 = fmaxf(mx1, __shfl_xor_sync(0xffffffffu, mx1, 2));
        const float mn0 = fmaxf(m0r, mx0), mn1 = fmaxf(m1r, mx1);
        const float sc0 = __expf(m0r - mn0), sc1 = __expf(m1r - mn1);
        float rs0 = 0.f, rs1 = 0.f;
#pragma unroll
        for (int j = 0; j < 8; j++) {
            s[j][0] = __expf(s[j][0] - mn0);
            s[j][1] = __expf(s[j][1] - mn0);
            s[j][2] = __expf(s[j][2] - mn1);
            s[j][3] = __expf(s[j][3] - mn1);
            rs0 += s[j][0] + s[j][1];
            rs1 += s[j][2] + s[j][3];
        }
        rs0 += __shfl_xor_sync(0xffffffffu, rs0, 1);
        rs0 += __shfl_xor_sync(0xffffffffu, rs0, 2);
        rs1 += __shfl_xor_sync(0xffffffffu, rs1, 1);
        rs1 += __shfl_xor_sync(0xffffffffu, rs1, 2);
        l0r = l0r * sc0 + rs0;
        l1r = l1r * sc1 + rs1;
        m0r = mn0; m1r = mn1;
#pragma unroll
        for (int j = 0; j < 8; j++) {
            o[j][0] *= sc0; o[j][1] *= sc0;
            o[j][2] *= sc1; o[j][3] *= sc1;
        }

        // ---- ctx += P @ V ----
#pragma unroll
        for (int ks = 0; ks < 4; ks++) {
            uint32_t pa[4];
            pa[0] = pack_h2(s[2*ks][0],   s[2*ks][1]);
            pa[1] = pack_h2(s[2*ks][2],   s[2*ks][3]);
            pa[2] = pack_h2(s[2*ks+1][0], s[2*ks+1][1]);
            pa[3] = pack_h2(s[2*ks+1][2], s[2*ks+1][3]);
#pragma unroll
            for (int d0 = 0; d0 < 4; d0++) {
                uint32_t vv[4];
                LDSM4T(vv, st + AT_QBUF + (16 * ks + vrow) * AT_PITCH + (d0 * 16 + vcol) * 2);
                const int dj = d0 * 2;
                mma_f16(o[dj],   pa, vv[0], vv[2]);
                mma_f16(o[dj+1], pa, vv[1], vv[3]);
            }
        }
    }

    // ---- write ctx half [b, s, h*64+d] ----
    const float rl0 = 1.0f / l0r, rl1 = 1.0f / l1r;
    const int row0 = b * S_ + qb + q0 + g;
    const int row1 = row0 + 8;
#pragma unroll
    for (int j = 0; j < 8; j++) {
        const int col = h * 64 + j * 8 + tig * 2;
        *reinterpret_cast<uint32_t*>(ctx + (size_t)row0 * M_ + col) = pack_h2(o[j][0]*rl0, o[j][1]*rl0);
        *reinterpret_cast<uint32_t*>(ctx + (size_t)row1 * M_ + col) = pack_h2(o[j][2]*rl1, o[j][3]*rl1);
    }
}

// ---------------- fused: attention CTAs + independent x@W1-top CTAs -------
#define GX_GEMM 512    // 8 n-tiles x 64 m-tiles
#define GX_ATTN 512    // 32 bh x 16 q-tiles
__global__ __launch_bounds__(256, 2)
void fused_attn_w1(const __half* __restrict__ xh, const __half* __restrict__ w1,
                   const float* __restrict__ b1, float* __restrict__ h2o,
                   const __half* __restrict__ qkv, const float* __restrict__ ocr,
                   __half* __restrict__ ctx)
{
    extern __shared__ char sm_[];
    if (blockIdx.x < GX_GEMM) {
        const int bm = (blockIdx.x & 63) * 128;
        const int bn = (blockIdx.x >> 6) * 128;
        hgemm_body<3>(sm_, bm, bn, xh, D_, D_, xh, D_,
                      w1, D_ + M_, b1, h2o, nullptr, D_, D_);
    } else {
        attn_body(sm_, blockIdx.x - GX_GEMM, qkv, ocr, ctx);
    }
}

// ---------------- layernorm ------------------------------------------------
__global__ __launch_bounds__(256)
void layernorm_k(const float* __restrict__ x, const float* __restrict__ g,
                 const float* __restrict__ bb, float* __restrict__ out)
{
    __shared__ float red[8];
    const int row = blockIdx.x, tid = threadIdx.x;
    const float4 v = reinterpret_cast<const float4*>(x + (size_t)row*1024)[tid];

    float s = v.x + v.y + v.z + v.w;
#pragma unroll
    for (int off = 16; off; off >>= 1) s += __shfl_xor_sync(0xffffffffu, s, off);
    if ((tid & 31) == 0) red[tid >> 5] = s;
    __syncthreads();
    if (tid < 32) {
        float t = (tid < 8) ? red[tid] : 0.f;
#pragma unroll
        for (int off = 4; off; off >>= 1) t += __shfl_xor_sync(0xffffffffu, t, off);
        if (tid == 0) red[0] = t;
    }
    __syncthreads();
    const float mean = red[0] * (1.0f / 1024.0f);
    const float dx = v.x - mean, dy = v.y - mean, dz = v.z - mean, dw = v.w - mean;
    float ss = dx*dx + dy*dy + dz*dz + dw*dw;
    __syncthreads();
#pragma unroll
    for (int off = 16; off; off >>= 1) ss += __shfl_xor_sync(0xffffffffu, ss, off);
    if ((tid & 31) == 0) red[tid >> 5] = ss;
    __syncthreads();
    if (tid < 32) {
        float t = (tid < 8) ? red[tid] : 0.f;
#pragma unroll
        for (int off = 4; off; off >>= 1) t += __shfl_xor_sync(0xffffffffu, t, off);
        if (tid == 0) red[0] = t;
    }
    __syncthreads();
    const float inv = rsqrtf(red[0] * (1.0f / 1024.0f) + 1e-5f);
    const int c = tid * 4;
    float4 o;
    o.x = dx * inv * g[c    ] + bb[c    ];
    o.y = dy * inv * g[c + 1] + bb[c + 1];
    o.z = dz * inv * g[c + 2] + bb[c + 2];
    o.w = dw * inv * g[c + 3] + bb[c + 3];
    reinterpret_cast<float4*>(out + (size_t)row*1024)[tid] = o;
}

// ---------------- launch ---------------------------------------------------
extern "C" void kernel_launch(void* const* d_in, const int* in_sizes, int n_in,
                              void* d_out, int out_size)
{
    const float* x     = (const float*)d_in[0];
    const float* W_enc = (const float*)d_in[1];
    const float* b_enc = (const float*)d_in[2];
    const float* Wq    = (const float*)d_in[3];
    const float* bq    = (const float*)d_in[4];
    const float* Wk    = (const float*)d_in[5];
    const float* bk    = (const float*)d_in[6];
    const float* Wv    = (const float*)d_in[7];
    const float* bv    = (const float*)d_in[8];
    const float* Wo    = (const float*)d_in[9];
    const float* bo    = (const float*)d_in[10];
    const float* ocr   = (const float*)d_in[11];
    const float* W1    = (const float*)d_in[12];
    const float* b1    = (const float*)d_in[13];
    const float* W2    = (const float*)d_in[14];
    const float* b2    = (const float*)d_in[15];
    const float* ln_g  = (const float*)d_in[16];
    const float* ln_b  = (const float*)d_in[17];
    float* out = (float*)d_out;

    __half *xh, *mem, *qkv, *ctx, *att, *h1;
    __half *wenc, *wqkv, *wo, *w1, *w2;
    float *h2, *bqkv;
    cudaGetSymbolAddress((void**)&xh,  g_x);
    cudaGetSymbolAddress((void**)&mem, g_mem);
    cudaGetSymbolAddress((void**)&qkv, g_qkv);
    cudaGetSymbolAddress((void**)&ctx, g_ctx);
    cudaGetSymbolAddress((void**)&att, g_att);
    cudaGetSymbolAddress((void**)&h1,  g_h1);
    cudaGetSymbolAddress((void**)&h2,  g_h2);
    cudaGetSymbolAddress((void**)&bqkv, g_bqkv);
    cudaGetSymbolAddress((void**)&wenc, g_wenc);
    cudaGetSymbolAddress((void**)&wqkv, g_wqkv);
    cudaGetSymbolAddress((void**)&wo, g_wo);
    cudaGetSymbolAddress((void**)&w1, g_w1);
    cudaGetSymbolAddress((void**)&w2, g_w2);

    cudaFuncSetAttribute(fused_attn_w1, cudaFuncAttributeMaxDynamicSharedMemorySize, GEMM_SMEM);
    cudaFuncSetAttribute(hgemm<0>, cudaFuncAttributeMaxDynamicSharedMemorySize, GEMM_SMEM);
    cudaFuncSetAttribute(hgemm<1>, cudaFuncAttributeMaxDynamicSharedMemorySize, GEMM_SMEM);
    cudaFuncSetAttribute(hgemm<3>, cudaFuncAttributeMaxDynamicSharedMemorySize, GEMM_SMEM);
    cudaFuncSetAttribute(hgemm<4>, cudaFuncAttributeMaxDynamicSharedMemorySize, GEMM_SMEM);

    // 1) prep: weights (transpose + fp16) + bias concat; x fp16
    prep_w<<<4096, dim3(32, 8)>>>(W_enc, Wq, Wk, Wv, Wo, W1, W2, bq, bk, bv);
    prep_x<<<8192, 256>>>(x);

    dim3 blk(256);
    // 2) mem = x @ W_enc + b_enc              K=1024
    hgemm<0><<<dim3(4, 64), blk, GEMM_SMEM>>>(xh, D_, D_, xh, D_, wenc, D_, b_enc,
                                              mem, nullptr, M_, D_);
    // 3) qkv = mem @ [Wq|Wk|Wv] + b -> scattered [3][B,H,S,64]  N=1536, K=512
    hgemm<1><<<dim3(12, 64), blk, GEMM_SMEM>>>(mem, M_, M_, mem, M_, wqkv, M_, bqkv,
                                               qkv, nullptr, 0, M_);
    // 4) FUSED: attention -> ctx  ||  h2 = x @ W1[:1024] + b1 (fp32)
    fused_attn_w1<<<GX_GEMM + GX_ATTN, blk, GEMM_SMEM>>>(xh, w1, b1, h2, qkv, ocr, ctx);
    // 5) att = ctx @ Wo + bo
    hgemm<0><<<dim3(4, 64), blk, GEMM_SMEM>>>(ctx, M_, M_, ctx, M_, wo, M_, bo,
                                              att, nullptr, M_, M_);
    // 6) h1 = gelu(h2 + att @ W1[1024:])      K=512
    hgemm<4><<<dim3(8, 64), blk, GEMM_SMEM>>>(att, M_, M_, att, M_, w1 + 1024, D_ + M_,
                                              nullptr, h1, h2, D_, M_);
    // 7) h2 = h1 @ W2 + b2 (fp32 out)
    hgemm<3><<<dim3(8, 64), blk, GEMM_SMEM>>>(h1, D_, D_, h1, D_, w2, D_, b2,
                                              h2, nullptr, D_, D_);
    // 8) layernorm
    layernorm_k<<<R_, blk>>>(h2, ln_g, ln_b, out);
}